// round 14
// baseline (speedup 1.0000x reference)
#include <cuda_runtime.h>
#include <cuda_fp16.h>
#include <cstdint>
#include <math.h>

#define BB  64
#define NV  2048
#define NQ  512
#define HH  256
#define HA  128
#define BC  16          // batches per pipeline chunk (4 chunks)

// ---------------- scratch (device globals) ---------------------------------
__device__ __half g_v16[(size_t)BB*NV*HH];
__device__ __half g_q16[(size_t)BB*NQ*HH];
__device__ __half g_WaT16[HH*HH];
__device__ __half g_Wv16[HA*HH], g_Wq16[HA*HH];
__device__ __half g_qW16[(size_t)BB*NQ*HH];
__device__ float  g_qb[BB*NQ];
__device__ __half g_pv16[(size_t)BB*NV*HA];
__device__ __half g_pvT16[(size_t)BB*HA*NV];
__device__ __half g_pq16[(size_t)BB*NQ*HA];
__device__ __half g_pqT16[(size_t)BB*HA*NQ];
__device__ __half g_aff16[(size_t)BB*NQ*NV];
__device__ __half g_afT16[(size_t)BB*NV*NQ];
__device__ float  g_lv[BB*NV], g_lq[BB*NQ];
__device__ float2 g_normv[BB], g_normq[BB];
__device__ float  g_partv[BB*8*HH], g_partq[BB*8*HH];

#define TILE_B   10240
#define BUF_B    (2 * TILE_B)
#define DYNSMEM  (2 * BUF_B)         // 40960
#define PLANE_B  33280

// ======================= low-level helpers =================================
__device__ __forceinline__ uint32_t smem_u32(const void* p) {
    uint32_t a;
    asm("{ .reg .u64 t; cvta.to.shared.u64 t, %1; cvt.u32.u64 %0, t; }"
        : "=r"(a) : "l"(p));
    return a;
}
__device__ __forceinline__ void ldsm4(uint32_t* r, uint32_t a) {
    asm volatile("ldmatrix.sync.aligned.m8n8.x4.shared.b16 {%0,%1,%2,%3}, [%4];"
                 : "=r"(r[0]), "=r"(r[1]), "=r"(r[2]), "=r"(r[3]) : "r"(a));
}
__device__ __forceinline__ void mma_f16(float* c, const uint32_t* a,
                                        const uint32_t* b) {
    asm volatile(
        "mma.sync.aligned.m16n8k16.row.col.f32.f16.f16.f32 "
        "{%0,%1,%2,%3}, {%4,%5,%6,%7}, {%8,%9}, {%0,%1,%2,%3};"
        : "+f"(c[0]), "+f"(c[1]), "+f"(c[2]), "+f"(c[3])
        : "r"(a[0]), "r"(a[1]), "r"(a[2]), "r"(a[3]), "r"(b[0]), "r"(b[1]));
}
__device__ __forceinline__ uint32_t cvt_h2(float x, float y) {
    uint32_t r;
    asm("cvt.rn.f16x2.f32 %0, %1, %2;" : "=r"(r) : "f"(y), "f"(x));
    return r;
}
__device__ __forceinline__ float tanh_fast(float x) {
    float e = __expf(2.0f * x);
    return 1.0f - __fdividef(2.0f, e + 1.0f);
}

__device__ __forceinline__ void stage_async(uint32_t buf,
        const __half* __restrict__ A, const __half* __restrict__ B,
        int lda, int ldb, int k0) {
    const int tid = threadIdx.x;
#pragma unroll
    for (int c = 0; c < 4; ++c) {
        const int lin = c * 256 + tid;
        const int sel = lin >> 9;
        const int li  = lin & 511;
        const int row = li >> 2, qt = li & 3;
        const __half* src = sel ? B : A;
        const int ld = sel ? ldb : lda;
        asm volatile("cp.async.cg.shared.global [%0], [%1], 16;"
            :: "r"(buf + sel * TILE_B + row * 80 + qt * 16),
               "l"((const char*)(src + (long)row * ld + k0) + qt * 16));
    }
}

__device__ __forceinline__ void plane_out(const uint16_t* __restrict__ sm,
                                          __half* __restrict__ dst,
                                          long row0, long col0, long ld, int tr) {
    const int tid = threadIdx.x;
#pragma unroll
    for (int cI = 0; cI < 8; ++cI) {
        const int g = cI * 256 + tid;
        const int r = g >> 4, ch = g & 15;
        uint16_t e[8];
#pragma unroll
        for (int i = 0; i < 8; ++i)
            e[i] = tr ? sm[(ch * 8 + i) * 130 + r] : sm[r * 130 + ch * 8 + i];
        uint4 w;
        w.x = e[0] | ((uint32_t)e[1] << 16);
        w.y = e[2] | ((uint32_t)e[3] << 16);
        w.z = e[4] | ((uint32_t)e[5] << 16);
        w.w = e[6] | ((uint32_t)e[7] << 16);
        *(uint4*)(dst + (row0 + r) * ld + col0 + ch * 8) = w;
    }
}

// ============================================================================
// prep kernels
// ============================================================================
__global__ __launch_bounds__(256)
void cvt_kernel(const float* __restrict__ x, __half* __restrict__ o, long n)
{
    const long i = ((long)blockIdx.x * 256 + threadIdx.x) * 4;
    if (i >= n) return;
    const float4 v = *(const float4*)(x + i);
    *(uint2*)((uint32_t*)o + (i >> 1)) =
        make_uint2(cvt_h2(v.x, v.y), cvt_h2(v.z, v.w));
}

__global__ __launch_bounds__(256)
void cvtT_kernel(const float* __restrict__ x, __half* __restrict__ o,
                 int R, int C)
{
    const int i = blockIdx.x * 256 + threadIdx.x;
    if (i >= R * C) return;
    const int r = i / C, c = i - r * C;
    o[(long)c * R + r] = __float2half(x[i]);
}

__global__ __launch_bounds__(256)
void qb_kernel(const float* __restrict__ q, const float* __restrict__ baff,
               float* __restrict__ qb, int rows)
{
    const int w = (blockIdx.x * 256 + threadIdx.x) >> 5;
    const int lane = threadIdx.x & 31;
    if (w >= rows) return;
    const float* r = q + (long)w * HH;
    float s = 0.f;
#pragma unroll
    for (int k = 0; k < 8; ++k)
        s += r[lane + 32 * k] * baff[lane + 32 * k];
#pragma unroll
    for (int off = 16; off > 0; off >>= 1)
        s += __shfl_xor_sync(0xffffffffu, s, off);
    if (lane == 0) qb[w] = s;
}

// ============================================================================
// mma2: C = A @ B^T (fp16 in, fp32 acc), 128x128x32 tile, 8 warps, 2 CTA/SM.
// MODE 0: C16 = f16(acc [+bias]) direct                      [qW]
// MODE 1: C16 = f16(acc + bias) + CT16 transposed (planes)   [pv,pq]
// MODE 2: C16 = f16(tanh(acc + rowB)) + CT16 transposed      [aff]
// MODE 3: logits[m] = Wh . tanh(f32(PAdd16[m]) + acc[m]) + bh
// ============================================================================
template<int MODE>
__global__ __launch_bounds__(256, 2)
void mma2(const __half* __restrict__ A, const __half* __restrict__ B,
          const float* __restrict__ bias, const float* __restrict__ rowB,
          __half* __restrict__ C16, __half* __restrict__ CT16,
          const __half* __restrict__ PAdd16,
          const float* __restrict__ Wh, const float* __restrict__ bh,
          float* __restrict__ logits,
          int K, int lda, int ldb, int ldC, int ldCT, int rpb,
          long sA, long sB, long sOC, long sOCT, long sPAdd, int sLog)
{
    extern __shared__ __align__(16) unsigned char smem_[];
    __shared__ float sPart[2][128];

    const int z = blockIdx.z;
    A += z * sA;  B += z * sB;
    if (MODE == 2) { C16 += z * sOC; CT16 += z * sOCT; rowB += (long)z * NQ; }
    if (MODE == 3) { PAdd16 += z * sPAdd; logits += (long)z * sLog; }

    const long m0 = (long)(MODE == 3 ? blockIdx.x : blockIdx.y) * 128;
    const long n0 = (MODE == 3) ? 0 : (long)blockIdx.x * 128;
    A += m0 * lda;  B += n0 * ldb;

    const uint32_t sb0 = smem_u32(smem_);
    const int tid = threadIdx.x;
    const int l = tid & 31, wid = tid >> 5;
    const int wm = wid & 3, wn = wid >> 2;

    const int sub = l >> 3, lr = l & 7;
    const uint32_t aRow = wm * 32 + ((sub & 1) << 3) + lr;
    const uint32_t aK   = (uint32_t)((sub >> 1) << 3);
    const uint32_t bRow = ((sub & 2) << 2) + lr;
    const uint32_t bK   = (uint32_t)((sub & 1) << 3);

    float acc[2][8][4] = {};

    stage_async(sb0, A, B, lda, ldb, 0);
    asm volatile("cp.async.commit_group;" ::: "memory");

    const int nchunk = K >> 5;
    for (int ch = 0; ch < nchunk; ++ch) {
        if (ch + 1 < nchunk) {
            stage_async(sb0 + ((ch + 1) & 1) * BUF_B, A, B, lda, ldb,
                        (ch + 1) * 32);
            asm volatile("cp.async.commit_group;" ::: "memory");
            asm volatile("cp.async.wait_group 1;" ::: "memory");
        } else {
            asm volatile("cp.async.wait_group 0;" ::: "memory");
        }
        __syncthreads();

        const uint32_t cur = sb0 + (ch & 1) * BUF_B;
        const uint32_t sA = cur, sB = cur + TILE_B;

#pragma unroll
        for (int kt = 0; kt < 32; kt += 16) {
            uint32_t Af[2][4];
            const uint32_t ak = (kt + aK) * 2;
#pragma unroll
            for (int mt = 0; mt < 2; ++mt)
                ldsm4(Af[mt], sA + (aRow + mt * 16) * 80 + ak);
            const uint32_t bk = (kt + bK) * 2;
#pragma unroll
            for (int g = 0; g < 4; ++g) {
                uint32_t Bf[4];
                ldsm4(Bf, sB + (wn * 64 + g * 16 + bRow) * 80 + bk);
                mma_f16(acc[0][2*g],   Af[0], &Bf[0]);
                mma_f16(acc[0][2*g+1], Af[0], &Bf[2]);
                mma_f16(acc[1][2*g],   Af[1], &Bf[0]);
                mma_f16(acc[1][2*g+1], Af[1], &Bf[2]);
            }
        }
        __syncthreads();
    }

    // ---------------- epilogues ----------------
    if (MODE == 0) {
#pragma unroll
        for (int mt = 0; mt < 2; ++mt) {
            const long r0 = m0 + wm * 32 + mt * 16 + (l >> 2);
#pragma unroll
            for (int nt = 0; nt < 8; ++nt) {
                const long col = n0 + wn * 64 + nt * 8 + 2 * (l & 3);
                float2 b2 = bias ? *(const float2*)&bias[col]
                                 : make_float2(0.f, 0.f);
                ((uint32_t*)C16)[(r0 * (long)ldC + col) >> 1] =
                    cvt_h2(acc[mt][nt][0] + b2.x, acc[mt][nt][1] + b2.y);
                ((uint32_t*)C16)[((r0 + 8) * (long)ldC + col) >> 1] =
                    cvt_h2(acc[mt][nt][2] + b2.x, acc[mt][nt][3] + b2.y);
            }
        }
    } else if (MODE == 1 || MODE == 2) {
        uint32_t* pl = (uint32_t*)smem_;
#pragma unroll
        for (int mt = 0; mt < 2; ++mt) {
            const int rl = wm * 32 + mt * 16 + (l >> 2);
            float rb0 = 0.f, rb1 = 0.f;
            if (MODE == 2) {
                rb0 = rowB[m0 + rl];
                rb1 = rowB[m0 + rl + 8];
            }
#pragma unroll
            for (int nt = 0; nt < 8; ++nt) {
                const int c = wn * 64 + nt * 8 + 2 * (l & 3);
                float v0 = acc[mt][nt][0], v1 = acc[mt][nt][1];
                float v2 = acc[mt][nt][2], v3 = acc[mt][nt][3];
                if (MODE == 1) {
                    const float2 b2 = *(const float2*)&bias[n0 + c];
                    v0 += b2.x; v1 += b2.y; v2 += b2.x; v3 += b2.y;
                } else {
                    v0 = tanh_fast(v0 + rb0); v1 = tanh_fast(v1 + rb0);
                    v2 = tanh_fast(v2 + rb1); v3 = tanh_fast(v3 + rb1);
                }
                pl[(rl * 130 + c) >> 1]       = cvt_h2(v0, v1);
                pl[((rl + 8) * 130 + c) >> 1] = cvt_h2(v2, v3);
            }
        }
        __syncthreads();
        const uint16_t* sm = (const uint16_t*)smem_;
        if (MODE == 1) {
            const long b = m0 / rpb, nIn = m0 - b * rpb;
            plane_out(sm, C16,  m0, 0, ldC, 0);
            plane_out(sm, CT16, b * HA, nIn, ldCT, 1);
        } else {
            plane_out(sm, C16,  m0, n0, ldC, 0);
            plane_out(sm, CT16, n0, m0, ldCT, 1);
        }
    } else {  // MODE 3
        float2 whr[8];
#pragma unroll
        for (int nt = 0; nt < 8; ++nt)
            whr[nt] = *(const float2*)&Wh[wn * 64 + nt * 8 + 2 * (l & 3)];
#pragma unroll
        for (int mt = 0; mt < 2; ++mt) {
            const int rr = wm * 32 + mt * 16 + (l >> 2);
            float s0 = 0.f, s1 = 0.f;
#pragma unroll
            for (int nt = 0; nt < 8; ++nt) {
                const int col = wn * 64 + nt * 8 + 2 * (l & 3);
                const float2 w = whr[nt];
                const float2 p0 = __half22float2(
                    *(const __half2*)&PAdd16[(m0 + rr) * (long)HA + col]);
                const float2 p1 = __half22float2(
                    *(const __half2*)&PAdd16[(m0 + rr + 8) * (long)HA + col]);
                s0 += w.x * tanh_fast(p0.x + acc[mt][nt][0])
                    + w.y * tanh_fast(p0.y + acc[mt][nt][1]);
                s1 += w.x * tanh_fast(p1.x + acc[mt][nt][2])
                    + w.y * tanh_fast(p1.y + acc[mt][nt][3]);
            }
            s0 += __shfl_xor_sync(0xffffffffu, s0, 1);
            s0 += __shfl_xor_sync(0xffffffffu, s0, 2);
            s1 += __shfl_xor_sync(0xffffffffu, s1, 1);
            s1 += __shfl_xor_sync(0xffffffffu, s1, 2);
            if ((l & 3) == 0) {
                sPart[wn][rr]     = s0;
                sPart[wn][rr + 8] = s1;
            }
        }
        __syncthreads();
        if (tid < 128)
            logits[m0 + tid] = sPart[0][tid] + sPart[1][tid] + bh[0];
    }
}

// ============================================================================
// Parallel softmax + weighted sum
// ============================================================================
__global__ __launch_bounds__(256)
void norm_kernel(const float* __restrict__ logits, float2* __restrict__ norm,
                 int N)
{
    const int b = blockIdx.x;
    logits += (long)b * N;
    __shared__ float sw[2048];
    __shared__ float red[256];
    const int tid = threadIdx.x;

    float mloc = -1e30f;
    for (int i = tid; i < N; i += 256) {
        float v = logits[i];
        sw[i] = v;
        mloc = fmaxf(mloc, v);
    }
    red[tid] = mloc;
    __syncthreads();
    for (int s = 128; s > 0; s >>= 1) {
        if (tid < s) red[tid] = fmaxf(red[tid], red[tid + s]);
        __syncthreads();
    }
    const float m = red[0];
    __syncthreads();

    float sloc = 0.f;
    for (int i = tid; i < N; i += 256)
        sloc += expf(sw[i] - m);
    red[tid] = sloc;
    __syncthreads();
    for (int s = 128; s > 0; s >>= 1) {
        if (tid < s) red[tid] += red[tid + s];
        __syncthreads();
    }
    if (tid == 0) norm[b] = make_float2(m, 1.f / red[0]);
}

__global__ __launch_bounds__(256)
void wsum_kernel(const float* __restrict__ logits, const float* __restrict__ X,
                 const float2* __restrict__ norm, float* __restrict__ part,
                 int N)
{
    const int b = blockIdx.y, c = blockIdx.x;
    const int CH = N >> 3;
    logits += (long)b * N + c * CH;
    X      += ((long)b * N + (long)c * CH) * HH;

    __shared__ float sw[256];
    const int tid = threadIdx.x;
    const float m = norm[b].x;
    for (int i = tid; i < CH; i += 256)
        sw[i] = expf(logits[i] - m);
    __syncthreads();

    float acc = 0.f;
#pragma unroll 4
    for (int n = 0; n < CH; ++n)
        acc = fmaf(sw[n], X[(long)n * HH + tid], acc);
    part[((b << 3) + c) * HH + tid] = acc;
}

__global__ __launch_bounds__(256)
void reduce_kernel(const float* __restrict__ part,
                   const float2* __restrict__ norm, float* __restrict__ out)
{
    const int b = blockIdx.x, tid = threadIdx.x;
    float s = 0.f;
#pragma unroll
    for (int c = 0; c < 8; ++c)
        s += part[((b << 3) + c) * HH + tid];
    out[(long)b * HH + tid] = s * norm[b].y;
}

// ============================================================================
extern "C" void kernel_launch(void* const* d_in, const int* in_sizes, int n_in,
                              void* d_out, int out_size)
{
    const float* v    = (const float*)d_in[0];
    const float* q    = (const float*)d_in[1];
    const float* Waff = (const float*)d_in[2];
    const float* baff = (const float*)d_in[3];
    const float* Wv   = (const float*)d_in[4];
    const float* bv   = (const float*)d_in[5];
    const float* Wq   = (const float*)d_in[6];
    const float* bq   = (const float*)d_in[7];
    const float* Whv  = (const float*)d_in[8];
    const float* bhv  = (const float*)d_in[9];
    const float* Whq  = (const float*)d_in[10];
    const float* bhq  = (const float*)d_in[11];
    float* out = (float*)d_out;

    __half *v16, *q16, *WaT16, *Wv16, *Wq16, *qW16, *pv16, *pvT16, *pq16,
           *pqT16, *aff16, *afT16;
    float *qb, *lv, *lq, *partv, *partq;
    float2 *nrmv, *nrmq;
    cudaGetSymbolAddress((void**)&v16,   g_v16);
    cudaGetSymbolAddress((void**)&q16,   g_q16);
    cudaGetSymbolAddress((void**)&WaT16, g_WaT16);
    cudaGetSymbolAddress((void**)&Wv16,  g_Wv16);
    cudaGetSymbolAddress((void**)&Wq16,  g_Wq16);
    cudaGetSymbolAddress((void**)&qW16,  g_qW16);
    cudaGetSymbolAddress((void**)&qb,    g_qb);
    cudaGetSymbolAddress((void**)&pv16,  g_pv16);
    cudaGetSymbolAddress((void**)&pvT16, g_pvT16);
    cudaGetSymbolAddress((void**)&pq16,  g_pq16);
    cudaGetSymbolAddress((void**)&pqT16, g_pqT16);
    cudaGetSymbolAddress((void**)&aff16, g_aff16);
    cudaGetSymbolAddress((void**)&afT16, g_afT16);
    cudaGetSymbolAddress((void**)&lv,    g_lv);
    cudaGetSymbolAddress((void**)&lq,    g_lq);
    cudaGetSymbolAddress((void**)&nrmv,  g_normv);
    cudaGetSymbolAddress((void**)&nrmq,  g_normq);
    cudaGetSymbolAddress((void**)&partv, g_partv);
    cudaGetSymbolAddress((void**)&partq, g_partq);

    cudaFuncSetAttribute(mma2<0>, cudaFuncAttributeMaxDynamicSharedMemorySize, DYNSMEM);
    cudaFuncSetAttribute(mma2<1>, cudaFuncAttributeMaxDynamicSharedMemorySize, DYNSMEM);
    cudaFuncSetAttribute(mma2<2>, cudaFuncAttributeMaxDynamicSharedMemorySize, DYNSMEM);
    cudaFuncSetAttribute(mma2<3>, cudaFuncAttributeMaxDynamicSharedMemorySize, DYNSMEM);

    // ---- 4 streams total (proven safe); 4 chunks round-robin on 2 pairs ---
    cudaStream_t sA[2], sB[2];
    cudaEvent_t eW, eV[2], ePV[2], eAFF[2], eOv[2], eOq[2];
    for (int p = 0; p < 2; ++p) {
        cudaStreamCreateWithFlags(&sA[p], cudaStreamNonBlocking);
        cudaStreamCreateWithFlags(&sB[p], cudaStreamNonBlocking);
        cudaEventCreateWithFlags(&eV[p],   cudaEventDisableTiming);
        cudaEventCreateWithFlags(&ePV[p],  cudaEventDisableTiming);
        cudaEventCreateWithFlags(&eAFF[p], cudaEventDisableTiming);
        cudaEventCreateWithFlags(&eOv[p],  cudaEventDisableTiming);
        cudaEventCreateWithFlags(&eOq[p],  cudaEventDisableTiming);
    }
    cudaEventCreateWithFlags(&eW, cudaEventDisableTiming);

    // weight preps on the capturing (default) stream
    cvtT_kernel<<<(HH*HH)/256, 256>>>(Waff, WaT16, HH, HH);
    cvt_kernel<<<(HA*HH)/1024, 256>>>(Wv, Wv16, HA*HH);
    cvt_kernel<<<(HA*HH)/1024, 256>>>(Wq, Wq16, HA*HH);
    cudaEventRecord(eW, 0);

    for (int c = 0; c < 4; ++c) {
        const int p = c & 1;
        const long z0 = (long)c * BC;
        const long oVH = z0 * NV * HH, oQH = z0 * NQ * HH;
        const long oPV = z0 * NV * HA, oPVT = z0 * HA * NV;
        const long oPQ = z0 * NQ * HA, oPQT = z0 * HA * NQ;
        const long oAF = z0 * NQ * NV, oAFT = z0 * NV * NQ;
        const long oLV = z0 * NV, oLQ = z0 * NQ;

        // sA: cvt_v -> pv(+pvT) -> [aff] -> G5 chain
        if (c < 2) cudaStreamWaitEvent(sA[p], eW, 0);
        cvt_kernel<<<(BC*NV*HH)/1024, 256, 0, sA[p]>>>(
            v + oVH, v16 + oVH, (long)BC*NV*HH);
        cudaEventRecord(eV[p], sA[p]);
        mma2<1><<<dim3(1, BC*NV/128, 1), 256, DYNSMEM, sA[p]>>>(
            v16 + oVH, Wv16, bv, nullptr, pv16 + oPV, pvT16 + oPVT, nullptr,
            nullptr, nullptr, nullptr,
            HH, HH, HH, HA, NV, NV, 0, 0, 0, 0, 0, 0);
        cudaEventRecord(ePV[p], sA[p]);

        // sB: cvt_q -> qb -> qW -> pq(+pqT) -> [v16] aff -> [pv] G6 chain
        if (c < 2) cudaStreamWaitEvent(sB[p], eW, 0);
        cvt_kernel<<<(BC*NQ*HH)/1024, 256, 0, sB[p]>>>(
            q + oQH, q16 + oQH, (long)BC*NQ*HH);
        qb_kernel<<<(BC*NQ)/8, 256, 0, sB[p]>>>(
            q + oQH, baff, qb + oLQ, BC*NQ);
        mma2<0><<<dim3(HH/128, BC*NQ/128, 1), 256, DYNSMEM, sB[p]>>>(
            q16 + oQH, WaT16, nullptr, nullptr, qW16 + oQH, nullptr, nullptr,
            nullptr, nullptr, nullptr,
            HH, HH, HH, HH, 0, 0, 0, 0, 0, 0, 0, 0);
        mma2<1><<<dim3(1, BC*NQ/128, 1), 256, DYNSMEM, sB[p]>>>(
            q16 + oQH, Wq16, bq, nullptr, pq16 + oPQ, pqT16 + oPQT, nullptr,
            nullptr, nullptr, nullptr,
            HH, HH, HH, HA, NQ, NQ, 0, 0, 0, 0, 0, 0);
        cudaStreamWaitEvent(sB[p], eV[p], 0);
        mma2<2><<<dim3(NV/128, NQ/128, BC), 256, DYNSMEM, sB[p]>>>(
            qW16 + oQH, v16 + oVH, nullptr, qb + oLQ,
            aff16 + oAF, afT16 + oAFT, nullptr, nullptr, nullptr, nullptr,
            HH, HH, HH, NV, NQ, 0,
            (long)NQ*HH, (long)NV*HH, (long)NQ*NV, (long)NV*NQ, 0, 0);
        cudaEventRecord(eAFF[p], sB[p]);

        // sA: G5 chain (aff event implies pq/pqT done; pv in-stream)
        cudaStreamWaitEvent(sA[p], eAFF[p], 0);
        mma2<3><<<dim3(NV/128, 1, BC), 256, DYNSMEM, sA[p]>>>(
            afT16 + oAFT, pqT16 + oPQT, nullptr, nullptr, nullptr, nullptr,
            pv16 + oPV, Whv, bhv, lv + oLV,
            NQ, NQ, NQ, 0, 0, 0,
            (long)NV*NQ, (long)HA*NQ, 0, 0, (long)NV*HA, NV);
        norm_kernel<<<BC, 256, 0, sA[p]>>>(lv + oLV, nrmv + z0, NV);
        wsum_kernel<<<dim3(8, BC), 256, 0, sA[p]>>>(
            lv + oLV, v + oVH, nrmv + z0, partv + z0*8*HH, NV);
        reduce_kernel<<<BC, 256, 0, sA[p]>>>(
            partv + z0*8*HH, nrmv + z0, out + z0*HH);
        cudaEventRecord(eOv[p], sA[p]);

        // sB: G6 chain (aff in-stream; needs pvT cross-stream)
        cudaStreamWaitEvent(sB[p], ePV[p], 0);
        mma2<3><<<dim3(NQ/128, 1, BC), 256, DYNSMEM, sB[p]>>>(
            aff16 + oAF, pvT16 + oPVT, nullptr, nullptr, nullptr, nullptr,
            pq16 + oPQ, Whq, bhq, lq + oLQ,
            NV, NV, NV, 0, 0, 0,
            (long)NQ*NV, (long)HA*NV, 0, 0, (long)NQ*HA, NQ);
        norm_kernel<<<BC, 256, 0, sB[p]>>>(lq + oLQ, nrmq + z0, NQ);
        wsum_kernel<<<dim3(8, BC), 256, 0, sB[p]>>>(
            lq + oLQ, q + oQH, nrmq + z0, partq + z0*8*HH, NQ);
        reduce_kernel<<<BC, 256, 0, sB[p]>>>(
            partq + z0*8*HH, nrmq + z0, out + (long)BB*HH + z0*HH);
        cudaEventRecord(eOq[p], sB[p]);

        // join the last two chunks into the capturing stream
        if (c >= 2) {
            cudaStreamWaitEvent(0, eOv[p], 0);
            cudaStreamWaitEvent(0, eOq[p], 0);
        }
    }

    for (int p = 0; p < 2; ++p) {
        cudaStreamDestroy(sA[p]); cudaStreamDestroy(sB[p]);
        cudaEventDestroy(eV[p]);  cudaEventDestroy(ePV[p]);
        cudaEventDestroy(eAFF[p]);
        cudaEventDestroy(eOv[p]); cudaEventDestroy(eOq[p]);
    }
    cudaEventDestroy(eW);
}

// round 15
// speedup vs baseline: 1.0951x; 1.0951x over previous
#include <cuda_runtime.h>
#include <cuda_fp16.h>
#include <cstdint>
#include <math.h>

#define BB  64
#define NV  2048
#define NQ  512
#define HH  256
#define HA  128
#define BH  32          // batches per pipeline half
#define BS  16          // batches per aff/G5 sub-launch

// ---------------- scratch (device globals) ---------------------------------
__device__ __half g_v16[(size_t)BB*NV*HH];
__device__ __half g_q16[(size_t)BB*NQ*HH];
__device__ __half g_WaT16[HH*HH];
__device__ __half g_Wv16[HA*HH], g_Wq16[HA*HH];
__device__ __half g_qW16[(size_t)BB*NQ*HH];
__device__ float  g_qb[BB*NQ];
__device__ __half g_pv16[(size_t)BB*NV*HA];
__device__ __half g_pvT16[(size_t)BB*HA*NV];
__device__ __half g_pq16[(size_t)BB*NQ*HA];
__device__ __half g_pqT16[(size_t)BB*HA*NQ];
__device__ __half g_aff16[(size_t)BB*NQ*NV];
__device__ __half g_afT16[(size_t)BB*NV*NQ];
__device__ float  g_lv[BB*NV], g_lq[BB*NQ];
__device__ float2 g_normv[BB], g_normq[BB];
__device__ float  g_partv[BB*8*HH], g_partq[BB*8*HH];

#define TILE_B   10240
#define BUF_B    (2 * TILE_B)
#define DYNSMEM  (2 * BUF_B)         // 40960
#define PLANE_B  33280

// ======================= low-level helpers =================================
__device__ __forceinline__ uint32_t smem_u32(const void* p) {
    uint32_t a;
    asm("{ .reg .u64 t; cvta.to.shared.u64 t, %1; cvt.u32.u64 %0, t; }"
        : "=r"(a) : "l"(p));
    return a;
}
__device__ __forceinline__ void ldsm4(uint32_t* r, uint32_t a) {
    asm volatile("ldmatrix.sync.aligned.m8n8.x4.shared.b16 {%0,%1,%2,%3}, [%4];"
                 : "=r"(r[0]), "=r"(r[1]), "=r"(r[2]), "=r"(r[3]) : "r"(a));
}
__device__ __forceinline__ void mma_f16(float* c, const uint32_t* a,
                                        const uint32_t* b) {
    asm volatile(
        "mma.sync.aligned.m16n8k16.row.col.f32.f16.f16.f32 "
        "{%0,%1,%2,%3}, {%4,%5,%6,%7}, {%8,%9}, {%0,%1,%2,%3};"
        : "+f"(c[0]), "+f"(c[1]), "+f"(c[2]), "+f"(c[3])
        : "r"(a[0]), "r"(a[1]), "r"(a[2]), "r"(a[3]), "r"(b[0]), "r"(b[1]));
}
__device__ __forceinline__ uint32_t cvt_h2(float x, float y) {
    uint32_t r;
    asm("cvt.rn.f16x2.f32 %0, %1, %2;" : "=r"(r) : "f"(y), "f"(x));
    return r;
}
__device__ __forceinline__ float tanh_fast(float x) {
    float e = __expf(2.0f * x);
    return 1.0f - __fdividef(2.0f, e + 1.0f);
}

__device__ __forceinline__ void stage_async(uint32_t buf,
        const __half* __restrict__ A, const __half* __restrict__ B,
        int lda, int ldb, int k0) {
    const int tid = threadIdx.x;
#pragma unroll
    for (int c = 0; c < 4; ++c) {
        const int lin = c * 256 + tid;
        const int sel = lin >> 9;
        const int li  = lin & 511;
        const int row = li >> 2, qt = li & 3;
        const __half* src = sel ? B : A;
        const int ld = sel ? ldb : lda;
        asm volatile("cp.async.cg.shared.global [%0], [%1], 16;"
            :: "r"(buf + sel * TILE_B + row * 80 + qt * 16),
               "l"((const char*)(src + (long)row * ld + k0) + qt * 16));
    }
}

__device__ __forceinline__ void plane_out(const uint16_t* __restrict__ sm,
                                          __half* __restrict__ dst,
                                          long row0, long col0, long ld, int tr) {
    const int tid = threadIdx.x;
#pragma unroll
    for (int cI = 0; cI < 8; ++cI) {
        const int g = cI * 256 + tid;
        const int r = g >> 4, ch = g & 15;
        uint16_t e[8];
#pragma unroll
        for (int i = 0; i < 8; ++i)
            e[i] = tr ? sm[(ch * 8 + i) * 130 + r] : sm[r * 130 + ch * 8 + i];
        uint4 w;
        w.x = e[0] | ((uint32_t)e[1] << 16);
        w.y = e[2] | ((uint32_t)e[3] << 16);
        w.z = e[4] | ((uint32_t)e[5] << 16);
        w.w = e[6] | ((uint32_t)e[7] << 16);
        *(uint4*)(dst + (row0 + r) * ld + col0 + ch * 8) = w;
    }
}

// ============================================================================
// prep kernels
// ============================================================================
__global__ __launch_bounds__(256)
void cvt_kernel(const float* __restrict__ x, __half* __restrict__ o, long n)
{
    const long i = ((long)blockIdx.x * 256 + threadIdx.x) * 4;
    if (i >= n) return;
    const float4 v = *(const float4*)(x + i);
    *(uint2*)((uint32_t*)o + (i >> 1)) =
        make_uint2(cvt_h2(v.x, v.y), cvt_h2(v.z, v.w));
}

__global__ __launch_bounds__(256)
void cvtT_kernel(const float* __restrict__ x, __half* __restrict__ o,
                 int R, int C)
{
    const int i = blockIdx.x * 256 + threadIdx.x;
    if (i >= R * C) return;
    const int r = i / C, c = i - r * C;
    o[(long)c * R + r] = __float2half(x[i]);
}

__global__ __launch_bounds__(256)
void qb_kernel(const float* __restrict__ q, const float* __restrict__ baff,
               float* __restrict__ qb, int rows)
{
    const int w = (blockIdx.x * 256 + threadIdx.x) >> 5;
    const int lane = threadIdx.x & 31;
    if (w >= rows) return;
    const float* r = q + (long)w * HH;
    float s = 0.f;
#pragma unroll
    for (int k = 0; k < 8; ++k)
        s += r[lane + 32 * k] * baff[lane + 32 * k];
#pragma unroll
    for (int off = 16; off > 0; off >>= 1)
        s += __shfl_xor_sync(0xffffffffu, s, off);
    if (lane == 0) qb[w] = s;
}

// ============================================================================
// mma2: C = A @ B^T (fp16 in, fp32 acc), 128x128x32 tile, 8 warps, 2 CTA/SM.
// MODE 0: C16 = f16(acc [+bias]) direct                      [qW]
// MODE 1: C16 = f16(acc + bias) + CT16 transposed (planes)   [pv,pq]
// MODE 2: C16 = f16(tanh(acc + rowB)) + CT16 transposed      [aff]
// MODE 3: logits[m] = Wh . tanh(f32(PAdd16[m]) + acc[m]) + bh
// ============================================================================
template<int MODE>
__global__ __launch_bounds__(256, 2)
void mma2(const __half* __restrict__ A, const __half* __restrict__ B,
          const float* __restrict__ bias, const float* __restrict__ rowB,
          __half* __restrict__ C16, __half* __restrict__ CT16,
          const __half* __restrict__ PAdd16,
          const float* __restrict__ Wh, const float* __restrict__ bh,
          float* __restrict__ logits,
          int K, int lda, int ldb, int ldC, int ldCT, int rpb,
          long sA, long sB, long sOC, long sOCT, long sPAdd, int sLog)
{
    extern __shared__ __align__(16) unsigned char smem_[];
    __shared__ float sPart[2][128];

    const int z = blockIdx.z;
    A += z * sA;  B += z * sB;
    if (MODE == 2) { C16 += z * sOC; CT16 += z * sOCT; rowB += (long)z * NQ; }
    if (MODE == 3) { PAdd16 += z * sPAdd; logits += (long)z * sLog; }

    const long m0 = (long)(MODE == 3 ? blockIdx.x : blockIdx.y) * 128;
    const long n0 = (MODE == 3) ? 0 : (long)blockIdx.x * 128;
    A += m0 * lda;  B += n0 * ldb;

    const uint32_t sb0 = smem_u32(smem_);
    const int tid = threadIdx.x;
    const int l = tid & 31, wid = tid >> 5;
    const int wm = wid & 3, wn = wid >> 2;

    const int sub = l >> 3, lr = l & 7;
    const uint32_t aRow = wm * 32 + ((sub & 1) << 3) + lr;
    const uint32_t aK   = (uint32_t)((sub >> 1) << 3);
    const uint32_t bRow = ((sub & 2) << 2) + lr;
    const uint32_t bK   = (uint32_t)((sub & 1) << 3);

    float acc[2][8][4] = {};

    stage_async(sb0, A, B, lda, ldb, 0);
    asm volatile("cp.async.commit_group;" ::: "memory");

    const int nchunk = K >> 5;
    for (int ch = 0; ch < nchunk; ++ch) {
        if (ch + 1 < nchunk) {
            stage_async(sb0 + ((ch + 1) & 1) * BUF_B, A, B, lda, ldb,
                        (ch + 1) * 32);
            asm volatile("cp.async.commit_group;" ::: "memory");
            asm volatile("cp.async.wait_group 1;" ::: "memory");
        } else {
            asm volatile("cp.async.wait_group 0;" ::: "memory");
        }
        __syncthreads();

        const uint32_t cur = sb0 + (ch & 1) * BUF_B;
        const uint32_t sA = cur, sB = cur + TILE_B;

#pragma unroll
        for (int kt = 0; kt < 32; kt += 16) {
            uint32_t Af[2][4];
            const uint32_t ak = (kt + aK) * 2;
#pragma unroll
            for (int mt = 0; mt < 2; ++mt)
                ldsm4(Af[mt], sA + (aRow + mt * 16) * 80 + ak);
            const uint32_t bk = (kt + bK) * 2;
#pragma unroll
            for (int g = 0; g < 4; ++g) {
                uint32_t Bf[4];
                ldsm4(Bf, sB + (wn * 64 + g * 16 + bRow) * 80 + bk);
                mma_f16(acc[0][2*g],   Af[0], &Bf[0]);
                mma_f16(acc[0][2*g+1], Af[0], &Bf[2]);
                mma_f16(acc[1][2*g],   Af[1], &Bf[0]);
                mma_f16(acc[1][2*g+1], Af[1], &Bf[2]);
            }
        }
        __syncthreads();
    }

    // ---------------- epilogues ----------------
    if (MODE == 0) {
#pragma unroll
        for (int mt = 0; mt < 2; ++mt) {
            const long r0 = m0 + wm * 32 + mt * 16 + (l >> 2);
#pragma unroll
            for (int nt = 0; nt < 8; ++nt) {
                const long col = n0 + wn * 64 + nt * 8 + 2 * (l & 3);
                float2 b2 = bias ? *(const float2*)&bias[col]
                                 : make_float2(0.f, 0.f);
                ((uint32_t*)C16)[(r0 * (long)ldC + col) >> 1] =
                    cvt_h2(acc[mt][nt][0] + b2.x, acc[mt][nt][1] + b2.y);
                ((uint32_t*)C16)[((r0 + 8) * (long)ldC + col) >> 1] =
                    cvt_h2(acc[mt][nt][2] + b2.x, acc[mt][nt][3] + b2.y);
            }
        }
    } else if (MODE == 1 || MODE == 2) {
        uint32_t* pl = (uint32_t*)smem_;
#pragma unroll
        for (int mt = 0; mt < 2; ++mt) {
            const int rl = wm * 32 + mt * 16 + (l >> 2);
            float rb0 = 0.f, rb1 = 0.f;
            if (MODE == 2) {
                rb0 = rowB[m0 + rl];
                rb1 = rowB[m0 + rl + 8];
            }
#pragma unroll
            for (int nt = 0; nt < 8; ++nt) {
                const int c = wn * 64 + nt * 8 + 2 * (l & 3);
                float v0 = acc[mt][nt][0], v1 = acc[mt][nt][1];
                float v2 = acc[mt][nt][2], v3 = acc[mt][nt][3];
                if (MODE == 1) {
                    const float2 b2 = *(const float2*)&bias[n0 + c];
                    v0 += b2.x; v1 += b2.y; v2 += b2.x; v3 += b2.y;
                } else {
                    v0 = tanh_fast(v0 + rb0); v1 = tanh_fast(v1 + rb0);
                    v2 = tanh_fast(v2 + rb1); v3 = tanh_fast(v3 + rb1);
                }
                pl[(rl * 130 + c) >> 1]       = cvt_h2(v0, v1);
                pl[((rl + 8) * 130 + c) >> 1] = cvt_h2(v2, v3);
            }
        }
        __syncthreads();
        const uint16_t* sm = (const uint16_t*)smem_;
        if (MODE == 1) {
            const long b = m0 / rpb, nIn = m0 - b * rpb;
            plane_out(sm, C16,  m0, 0, ldC, 0);
            plane_out(sm, CT16, b * HA, nIn, ldCT, 1);
        } else {
            plane_out(sm, C16,  m0, n0, ldC, 0);
            plane_out(sm, CT16, n0, m0, ldCT, 1);
        }
    } else {  // MODE 3
        float2 whr[8];
#pragma unroll
        for (int nt = 0; nt < 8; ++nt)
            whr[nt] = *(const float2*)&Wh[wn * 64 + nt * 8 + 2 * (l & 3)];
#pragma unroll
        for (int mt = 0; mt < 2; ++mt) {
            const int rr = wm * 32 + mt * 16 + (l >> 2);
            float s0 = 0.f, s1 = 0.f;
#pragma unroll
            for (int nt = 0; nt < 8; ++nt) {
                const int col = wn * 64 + nt * 8 + 2 * (l & 3);
                const float2 w = whr[nt];
                const float2 p0 = __half22float2(
                    *(const __half2*)&PAdd16[(m0 + rr) * (long)HA + col]);
                const float2 p1 = __half22float2(
                    *(const __half2*)&PAdd16[(m0 + rr + 8) * (long)HA + col]);
                s0 += w.x * tanh_fast(p0.x + acc[mt][nt][0])
                    + w.y * tanh_fast(p0.y + acc[mt][nt][1]);
                s1 += w.x * tanh_fast(p1.x + acc[mt][nt][2])
                    + w.y * tanh_fast(p1.y + acc[mt][nt][3]);
            }
            s0 += __shfl_xor_sync(0xffffffffu, s0, 1);
            s0 += __shfl_xor_sync(0xffffffffu, s0, 2);
            s1 += __shfl_xor_sync(0xffffffffu, s1, 1);
            s1 += __shfl_xor_sync(0xffffffffu, s1, 2);
            if ((l & 3) == 0) {
                sPart[wn][rr]     = s0;
                sPart[wn][rr + 8] = s1;
            }
        }
        __syncthreads();
        if (tid < 128)
            logits[m0 + tid] = sPart[0][tid] + sPart[1][tid] + bh[0];
    }
}

// ============================================================================
// Parallel softmax + weighted sum
// ============================================================================
__global__ __launch_bounds__(256)
void norm_kernel(const float* __restrict__ logits, float2* __restrict__ norm,
                 int N)
{
    const int b = blockIdx.x;
    logits += (long)b * N;
    __shared__ float sw[2048];
    __shared__ float red[256];
    const int tid = threadIdx.x;

    float mloc = -1e30f;
    for (int i = tid; i < N; i += 256) {
        float v = logits[i];
        sw[i] = v;
        mloc = fmaxf(mloc, v);
    }
    red[tid] = mloc;
    __syncthreads();
    for (int s = 128; s > 0; s >>= 1) {
        if (tid < s) red[tid] = fmaxf(red[tid], red[tid + s]);
        __syncthreads();
    }
    const float m = red[0];
    __syncthreads();

    float sloc = 0.f;
    for (int i = tid; i < N; i += 256)
        sloc += expf(sw[i] - m);
    red[tid] = sloc;
    __syncthreads();
    for (int s = 128; s > 0; s >>= 1) {
        if (tid < s) red[tid] += red[tid + s];
        __syncthreads();
    }
    if (tid == 0) norm[b] = make_float2(m, 1.f / red[0]);
}

__global__ __launch_bounds__(256)
void wsum_kernel(const float* __restrict__ logits, const float* __restrict__ X,
                 const float2* __restrict__ norm, float* __restrict__ part,
                 int N)
{
    const int b = blockIdx.y, c = blockIdx.x;
    const int CH = N >> 3;
    logits += (long)b * N + c * CH;
    X      += ((long)b * N + (long)c * CH) * HH;

    __shared__ float sw[256];
    const int tid = threadIdx.x;
    const float m = norm[b].x;
    for (int i = tid; i < CH; i += 256)
        sw[i] = expf(logits[i] - m);
    __syncthreads();

    float acc = 0.f;
#pragma unroll 4
    for (int n = 0; n < CH; ++n)
        acc = fmaf(sw[n], X[(long)n * HH + tid], acc);
    part[((b << 3) + c) * HH + tid] = acc;
}

__global__ __launch_bounds__(256)
void reduce_kernel(const float* __restrict__ part,
                   const float2* __restrict__ norm, float* __restrict__ out)
{
    const int b = blockIdx.x, tid = threadIdx.x;
    float s = 0.f;
#pragma unroll
    for (int c = 0; c < 8; ++c)
        s += part[((b << 3) + c) * HH + tid];
    out[(long)b * HH + tid] = s * norm[b].y;
}

// ============================================================================
extern "C" void kernel_launch(void* const* d_in, const int* in_sizes, int n_in,
                              void* d_out, int out_size)
{
    const float* v    = (const float*)d_in[0];
    const float* q    = (const float*)d_in[1];
    const float* Waff = (const float*)d_in[2];
    const float* baff = (const float*)d_in[3];
    const float* Wv   = (const float*)d_in[4];
    const float* bv   = (const float*)d_in[5];
    const float* Wq   = (const float*)d_in[6];
    const float* bq   = (const float*)d_in[7];
    const float* Whv  = (const float*)d_in[8];
    const float* bhv  = (const float*)d_in[9];
    const float* Whq  = (const float*)d_in[10];
    const float* bhq  = (const float*)d_in[11];
    float* out = (float*)d_out;

    __half *v16, *q16, *WaT16, *Wv16, *Wq16, *qW16, *pv16, *pvT16, *pq16,
           *pqT16, *aff16, *afT16;
    float *qb, *lv, *lq, *partv, *partq;
    float2 *nrmv, *nrmq;
    cudaGetSymbolAddress((void**)&v16,   g_v16);
    cudaGetSymbolAddress((void**)&q16,   g_q16);
    cudaGetSymbolAddress((void**)&WaT16, g_WaT16);
    cudaGetSymbolAddress((void**)&Wv16,  g_Wv16);
    cudaGetSymbolAddress((void**)&Wq16,  g_Wq16);
    cudaGetSymbolAddress((void**)&qW16,  g_qW16);
    cudaGetSymbolAddress((void**)&qb,    g_qb);
    cudaGetSymbolAddress((void**)&pv16,  g_pv16);
    cudaGetSymbolAddress((void**)&pvT16, g_pvT16);
    cudaGetSymbolAddress((void**)&pq16,  g_pq16);
    cudaGetSymbolAddress((void**)&pqT16, g_pqT16);
    cudaGetSymbolAddress((void**)&aff16, g_aff16);
    cudaGetSymbolAddress((void**)&afT16, g_afT16);
    cudaGetSymbolAddress((void**)&lv,    g_lv);
    cudaGetSymbolAddress((void**)&lq,    g_lq);
    cudaGetSymbolAddress((void**)&nrmv,  g_normv);
    cudaGetSymbolAddress((void**)&nrmq,  g_normq);
    cudaGetSymbolAddress((void**)&partv, g_partv);
    cudaGetSymbolAddress((void**)&partq, g_partq);

    cudaFuncSetAttribute(mma2<0>, cudaFuncAttributeMaxDynamicSharedMemorySize, DYNSMEM);
    cudaFuncSetAttribute(mma2<1>, cudaFuncAttributeMaxDynamicSharedMemorySize, DYNSMEM);
    cudaFuncSetAttribute(mma2<2>, cudaFuncAttributeMaxDynamicSharedMemorySize, DYNSMEM);
    cudaFuncSetAttribute(mma2<3>, cudaFuncAttributeMaxDynamicSharedMemorySize, DYNSMEM);

    // ---- 4 streams (proven safe), 2 per half; aff/G5 sub-split via events --
    cudaStream_t sA[2], sB[2];
    cudaEvent_t eW, eV[2], ePV[2], eAFFa[2], eAFFb[2], eOv[2], eOq[2];
    for (int h = 0; h < 2; ++h) {
        cudaStreamCreateWithFlags(&sA[h], cudaStreamNonBlocking);
        cudaStreamCreateWithFlags(&sB[h], cudaStreamNonBlocking);
        cudaEventCreateWithFlags(&eV[h],    cudaEventDisableTiming);
        cudaEventCreateWithFlags(&ePV[h],   cudaEventDisableTiming);
        cudaEventCreateWithFlags(&eAFFa[h], cudaEventDisableTiming);
        cudaEventCreateWithFlags(&eAFFb[h], cudaEventDisableTiming);
        cudaEventCreateWithFlags(&eOv[h],   cudaEventDisableTiming);
        cudaEventCreateWithFlags(&eOq[h],   cudaEventDisableTiming);
    }
    cudaEventCreateWithFlags(&eW, cudaEventDisableTiming);

    // weight preps on the capturing (default) stream
    cvtT_kernel<<<(HH*HH)/256, 256>>>(Waff, WaT16, HH, HH);
    cvt_kernel<<<(HA*HH)/1024, 256>>>(Wv, Wv16, HA*HH);
    cvt_kernel<<<(HA*HH)/1024, 256>>>(Wq, Wq16, HA*HH);
    cudaEventRecord(eW, 0);

    for (int h = 0; h < 2; ++h) {
        const long z0 = (long)h * BH;
        const long oVH = z0 * NV * HH, oQH = z0 * NQ * HH;
        const long oPV = z0 * NV * HA, oPVT = z0 * HA * NV;
        const long oPQ = z0 * NQ * HA, oPQT = z0 * HA * NQ;
        const long oLQ = z0 * NQ;

        // sA: cvt_v -> pv(+pvT) -> [aff subs] -> G5 subs + v-softmax subs
        cudaStreamWaitEvent(sA[h], eW, 0);
        cvt_kernel<<<(BH*NV*HH)/1024, 256, 0, sA[h]>>>(
            v + oVH, v16 + oVH, (long)BH*NV*HH);
        cudaEventRecord(eV[h], sA[h]);
        mma2<1><<<dim3(1, BH*NV/128, 1), 256, DYNSMEM, sA[h]>>>(
            v16 + oVH, Wv16, bv, nullptr, pv16 + oPV, pvT16 + oPVT, nullptr,
            nullptr, nullptr, nullptr,
            HH, HH, HH, HA, NV, NV, 0, 0, 0, 0, 0, 0);
        cudaEventRecord(ePV[h], sA[h]);

        // sB: cvt_q -> qb -> qW -> pq(+pqT) -> [v16] aff_a, aff_b -> [pv] G6
        cudaStreamWaitEvent(sB[h], eW, 0);
        cvt_kernel<<<(BH*NQ*HH)/1024, 256, 0, sB[h]>>>(
            q + oQH, q16 + oQH, (long)BH*NQ*HH);
        qb_kernel<<<(BH*NQ)/8, 256, 0, sB[h]>>>(
            q + oQH, baff, qb + oLQ, BH*NQ);
        mma2<0><<<dim3(HH/128, BH*NQ/128, 1), 256, DYNSMEM, sB[h]>>>(
            q16 + oQH, WaT16, nullptr, nullptr, qW16 + oQH, nullptr, nullptr,
            nullptr, nullptr, nullptr,
            HH, HH, HH, HH, 0, 0, 0, 0, 0, 0, 0, 0);
        mma2<1><<<dim3(1, BH*NQ/128, 1), 256, DYNSMEM, sB[h]>>>(
            q16 + oQH, Wq16, bq, nullptr, pq16 + oPQ, pqT16 + oPQT, nullptr,
            nullptr, nullptr, nullptr,
            HH, HH, HH, HA, NQ, NQ, 0, 0, 0, 0, 0, 0);
        cudaStreamWaitEvent(sB[h], eV[h], 0);

        // aff sub-launches (z = 16 each), events after each
        for (int s = 0; s < 2; ++s) {
            const long zs = z0 + (long)s * BS;
            mma2<2><<<dim3(NV/128, NQ/128, BS), 256, DYNSMEM, sB[h]>>>(
                qW16 + zs*NQ*HH, v16 + zs*NV*HH, nullptr, qb + zs*NQ,
                aff16 + zs*NQ*NV, afT16 + zs*NV*NQ, nullptr,
                nullptr, nullptr, nullptr,
                HH, HH, HH, NV, NQ, 0,
                (long)NQ*HH, (long)NV*HH, (long)NQ*NV, (long)NV*NQ, 0, 0);
            cudaEventRecord(s == 0 ? eAFFa[h] : eAFFb[h], sB[h]);
        }

        // sA: G5 + v-softmax per sub (sub-0 overlaps aff sub-1)
        for (int s = 0; s < 2; ++s) {
            const long zs = z0 + (long)s * BS;
            cudaStreamWaitEvent(sA[h], s == 0 ? eAFFa[h] : eAFFb[h], 0);
            mma2<3><<<dim3(NV/128, 1, BS), 256, DYNSMEM, sA[h]>>>(
                afT16 + zs*NV*NQ, pqT16 + zs*HA*NQ, nullptr, nullptr,
                nullptr, nullptr, pv16 + zs*NV*HA, Whv, bhv, lv + zs*NV,
                NQ, NQ, NQ, 0, 0, 0,
                (long)NV*NQ, (long)HA*NQ, 0, 0, (long)NV*HA, NV);
            norm_kernel<<<BS, 256, 0, sA[h]>>>(lv + zs*NV, nrmv + zs, NV);
            wsum_kernel<<<dim3(8, BS), 256, 0, sA[h]>>>(
                lv + zs*NV, v + zs*NV*HH, nrmv + zs, partv + zs*8*HH, NV);
            reduce_kernel<<<BS, 256, 0, sA[h]>>>(
                partv + zs*8*HH, nrmv + zs, out + zs*HH);
        }
        cudaEventRecord(eOv[h], sA[h]);

        // sB: G6 chain (aff_b in-stream; needs pvT cross-stream)
        cudaStreamWaitEvent(sB[h], ePV[h], 0);
        mma2<3><<<dim3(NQ/128, 1, BH), 256, DYNSMEM, sB[h]>>>(
            aff16 + z0*NQ*NV, pvT16 + oPVT, nullptr, nullptr, nullptr, nullptr,
            pq16 + oPQ, Whq, bhq, lq + oLQ,
            NV, NV, NV, 0, 0, 0,
            (long)NQ*NV, (long)HA*NV, 0, 0, (long)NQ*HA, NQ);
        norm_kernel<<<BH, 256, 0, sB[h]>>>(lq + oLQ, nrmq + z0, NQ);
        wsum_kernel<<<dim3(8, BH), 256, 0, sB[h]>>>(
            lq + oLQ, q + oQH, nrmq + z0, partq + z0*8*HH, NQ);
        reduce_kernel<<<BH, 256, 0, sB[h]>>>(
            partq + z0*8*HH, nrmq + z0, out + (long)BB*HH + z0*HH);
        cudaEventRecord(eOq[h], sB[h]);
    }

    for (int h = 0; h < 2; ++h) {
        cudaStreamWaitEvent(0, eOv[h], 0);
        cudaStreamWaitEvent(0, eOq[h], 0);
    }

    for (int h = 0; h < 2; ++h) {
        cudaStreamDestroy(sA[h]); cudaStreamDestroy(sB[h]);
        cudaEventDestroy(eV[h]);   cudaEventDestroy(ePV[h]);
        cudaEventDestroy(eAFFa[h]); cudaEventDestroy(eAFFb[h]);
        cudaEventDestroy(eOv[h]);  cudaEventDestroy(eOq[h]);
    }
    cudaEventDestroy(eW);
}

// round 16
// speedup vs baseline: 1.1859x; 1.0828x over previous
#include <cuda_runtime.h>
#include <cuda_fp16.h>
#include <cstdint>
#include <math.h>

#define BB  64
#define NV  2048
#define NQ  512
#define HH  256
#define HA  128
#define BH  32          // batches per pipeline half

// ---------------- scratch (device globals) ---------------------------------
__device__ __half g_v16[(size_t)BB*NV*HH];
__device__ __half g_q16[(size_t)BB*NQ*HH];
__device__ __half g_WaT16[HH*HH];
__device__ __half g_Wv16[HA*HH], g_Wq16[HA*HH];
__device__ __half g_qW16[(size_t)BB*NQ*HH];
__device__ float  g_qb[BB*NQ];
__device__ __half g_pv16[(size_t)BB*NV*HA];
__device__ __half g_pvT16[(size_t)BB*HA*NV];
__device__ __half g_pq16[(size_t)BB*NQ*HA];
__device__ __half g_pqT16[(size_t)BB*HA*NQ];
__device__ __half g_aff16[(size_t)BB*NQ*NV];
__device__ __half g_afT16[(size_t)BB*NV*NQ];
__device__ float  g_lv[BB*NV], g_lq[BB*NQ];
__device__ float2 g_normv[BB], g_normq[BB];
__device__ float  g_partv[BB*8*HH], g_partq[BB*8*HH];

#define TILE_B   10240
#define BUF_B    (2 * TILE_B)
#define DYNSMEM  (2 * BUF_B)         // 40960
#define PLANE_B  33280

// ======================= low-level helpers =================================
__device__ __forceinline__ uint32_t smem_u32(const void* p) {
    uint32_t a;
    asm("{ .reg .u64 t; cvta.to.shared.u64 t, %1; cvt.u32.u64 %0, t; }"
        : "=r"(a) : "l"(p));
    return a;
}
__device__ __forceinline__ void ldsm4(uint32_t* r, uint32_t a) {
    asm volatile("ldmatrix.sync.aligned.m8n8.x4.shared.b16 {%0,%1,%2,%3}, [%4];"
                 : "=r"(r[0]), "=r"(r[1]), "=r"(r[2]), "=r"(r[3]) : "r"(a));
}
__device__ __forceinline__ void mma_f16(float* c, const uint32_t* a,
                                        const uint32_t* b) {
    asm volatile(
        "mma.sync.aligned.m16n8k16.row.col.f32.f16.f16.f32 "
        "{%0,%1,%2,%3}, {%4,%5,%6,%7}, {%8,%9}, {%0,%1,%2,%3};"
        : "+f"(c[0]), "+f"(c[1]), "+f"(c[2]), "+f"(c[3])
        : "r"(a[0]), "r"(a[1]), "r"(a[2]), "r"(a[3]), "r"(b[0]), "r"(b[1]));
}
__device__ __forceinline__ uint32_t cvt_h2(float x, float y) {
    uint32_t r;
    asm("cvt.rn.f16x2.f32 %0, %1, %2;" : "=r"(r) : "f"(y), "f"(x));
    return r;
}
__device__ __forceinline__ float tanh_fast(float x) {
    float e = __expf(2.0f * x);
    return 1.0f - __fdividef(2.0f, e + 1.0f);
}

__device__ __forceinline__ void stage_async(uint32_t buf,
        const __half* __restrict__ A, const __half* __restrict__ B,
        int lda, int ldb, int k0) {
    const int tid = threadIdx.x;
#pragma unroll
    for (int c = 0; c < 4; ++c) {
        const int lin = c * 256 + tid;
        const int sel = lin >> 9;
        const int li  = lin & 511;
        const int row = li >> 2, qt = li & 3;
        const __half* src = sel ? B : A;
        const int ld = sel ? ldb : lda;
        asm volatile("cp.async.cg.shared.global [%0], [%1], 16;"
            :: "r"(buf + sel * TILE_B + row * 80 + qt * 16),
               "l"((const char*)(src + (long)row * ld + k0) + qt * 16));
    }
}

__device__ __forceinline__ void plane_out(const uint16_t* __restrict__ sm,
                                          __half* __restrict__ dst,
                                          long row0, long col0, long ld, int tr) {
    const int tid = threadIdx.x;
#pragma unroll
    for (int cI = 0; cI < 8; ++cI) {
        const int g = cI * 256 + tid;
        const int r = g >> 4, ch = g & 15;
        uint16_t e[8];
#pragma unroll
        for (int i = 0; i < 8; ++i)
            e[i] = tr ? sm[(ch * 8 + i) * 130 + r] : sm[r * 130 + ch * 8 + i];
        uint4 w;
        w.x = e[0] | ((uint32_t)e[1] << 16);
        w.y = e[2] | ((uint32_t)e[3] << 16);
        w.z = e[4] | ((uint32_t)e[5] << 16);
        w.w = e[6] | ((uint32_t)e[7] << 16);
        *(uint4*)(dst + (row0 + r) * ld + col0 + ch * 8) = w;
    }
}

// ============================================================================
// prep kernels
// ============================================================================
__global__ __launch_bounds__(256)
void cvt_kernel(const float* __restrict__ x, __half* __restrict__ o, long n)
{
    const long i = ((long)blockIdx.x * 256 + threadIdx.x) * 4;
    if (i >= n) return;
    const float4 v = *(const float4*)(x + i);
    *(uint2*)((uint32_t*)o + (i >> 1)) =
        make_uint2(cvt_h2(v.x, v.y), cvt_h2(v.z, v.w));
}

__global__ __launch_bounds__(256)
void cvtT_kernel(const float* __restrict__ x, __half* __restrict__ o,
                 int R, int C)
{
    const int i = blockIdx.x * 256 + threadIdx.x;
    if (i >= R * C) return;
    const int r = i / C, c = i - r * C;
    o[(long)c * R + r] = __float2half(x[i]);
}

__global__ __launch_bounds__(256)
void qb_kernel(const float* __restrict__ q, const float* __restrict__ baff,
               float* __restrict__ qb, int rows)
{
    const int w = (blockIdx.x * 256 + threadIdx.x) >> 5;
    const int lane = threadIdx.x & 31;
    if (w >= rows) return;
    const float* r = q + (long)w * HH;
    float s = 0.f;
#pragma unroll
    for (int k = 0; k < 8; ++k)
        s += r[lane + 32 * k] * baff[lane + 32 * k];
#pragma unroll
    for (int off = 16; off > 0; off >>= 1)
        s += __shfl_xor_sync(0xffffffffu, s, off);
    if (lane == 0) qb[w] = s;
}

// ============================================================================
// mma2: C = A @ B^T (fp16 in, fp32 acc), 128x128x32 tile, 8 warps, 2 CTA/SM.
// MODE 0: C16 = f16(acc [+bias]) direct                      [qW]
// MODE 1: C16 = f16(acc + bias) + CT16 transposed (planes)   [pv,pq]
// MODE 2: C16 = f16(tanh(acc + rowB)) + CT16 transposed      [aff]
// MODE 3: logits[m] = Wh . tanh(f32(PAdd16[m]) + acc[m]) + bh
// ============================================================================
template<int MODE>
__global__ __launch_bounds__(256, 2)
void mma2(const __half* __restrict__ A, const __half* __restrict__ B,
          const float* __restrict__ bias, const float* __restrict__ rowB,
          __half* __restrict__ C16, __half* __restrict__ CT16,
          const __half* __restrict__ PAdd16,
          const float* __restrict__ Wh, const float* __restrict__ bh,
          float* __restrict__ logits,
          int K, int lda, int ldb, int ldC, int ldCT, int rpb,
          long sA, long sB, long sOC, long sOCT, long sPAdd, int sLog)
{
    extern __shared__ __align__(16) unsigned char smem_[];
    __shared__ float sPart[2][128];

    const int z = blockIdx.z;
    A += z * sA;  B += z * sB;
    if (MODE == 2) { C16 += z * sOC; CT16 += z * sOCT; rowB += (long)z * NQ; }
    if (MODE == 3) { PAdd16 += z * sPAdd; logits += (long)z * sLog; }

    const long m0 = (long)(MODE == 3 ? blockIdx.x : blockIdx.y) * 128;
    const long n0 = (MODE == 3) ? 0 : (long)blockIdx.x * 128;
    A += m0 * lda;  B += n0 * ldb;

    const uint32_t sb0 = smem_u32(smem_);
    const int tid = threadIdx.x;
    const int l = tid & 31, wid = tid >> 5;
    const int wm = wid & 3, wn = wid >> 2;

    const int sub = l >> 3, lr = l & 7;
    const uint32_t aRow = wm * 32 + ((sub & 1) << 3) + lr;
    const uint32_t aK   = (uint32_t)((sub >> 1) << 3);
    const uint32_t bRow = ((sub & 2) << 2) + lr;
    const uint32_t bK   = (uint32_t)((sub & 1) << 3);

    float acc[2][8][4] = {};

    stage_async(sb0, A, B, lda, ldb, 0);
    asm volatile("cp.async.commit_group;" ::: "memory");

    const int nchunk = K >> 5;
    for (int ch = 0; ch < nchunk; ++ch) {
        if (ch + 1 < nchunk) {
            stage_async(sb0 + ((ch + 1) & 1) * BUF_B, A, B, lda, ldb,
                        (ch + 1) * 32);
            asm volatile("cp.async.commit_group;" ::: "memory");
            asm volatile("cp.async.wait_group 1;" ::: "memory");
        } else {
            asm volatile("cp.async.wait_group 0;" ::: "memory");
        }
        __syncthreads();

        const uint32_t cur = sb0 + (ch & 1) * BUF_B;
        const uint32_t sA = cur, sB = cur + TILE_B;

#pragma unroll
        for (int kt = 0; kt < 32; kt += 16) {
            uint32_t Af[2][4];
            const uint32_t ak = (kt + aK) * 2;
#pragma unroll
            for (int mt = 0; mt < 2; ++mt)
                ldsm4(Af[mt], sA + (aRow + mt * 16) * 80 + ak);
            const uint32_t bk = (kt + bK) * 2;
#pragma unroll
            for (int g = 0; g < 4; ++g) {
                uint32_t Bf[4];
                ldsm4(Bf, sB + (wn * 64 + g * 16 + bRow) * 80 + bk);
                mma_f16(acc[0][2*g],   Af[0], &Bf[0]);
                mma_f16(acc[0][2*g+1], Af[0], &Bf[2]);
                mma_f16(acc[1][2*g],   Af[1], &Bf[0]);
                mma_f16(acc[1][2*g+1], Af[1], &Bf[2]);
            }
        }
        __syncthreads();
    }

    // ---------------- epilogues ----------------
    if (MODE == 0) {
#pragma unroll
        for (int mt = 0; mt < 2; ++mt) {
            const long r0 = m0 + wm * 32 + mt * 16 + (l >> 2);
#pragma unroll
            for (int nt = 0; nt < 8; ++nt) {
                const long col = n0 + wn * 64 + nt * 8 + 2 * (l & 3);
                float2 b2 = bias ? *(const float2*)&bias[col]
                                 : make_float2(0.f, 0.f);
                ((uint32_t*)C16)[(r0 * (long)ldC + col) >> 1] =
                    cvt_h2(acc[mt][nt][0] + b2.x, acc[mt][nt][1] + b2.y);
                ((uint32_t*)C16)[((r0 + 8) * (long)ldC + col) >> 1] =
                    cvt_h2(acc[mt][nt][2] + b2.x, acc[mt][nt][3] + b2.y);
            }
        }
    } else if (MODE == 1 || MODE == 2) {
        uint32_t* pl = (uint32_t*)smem_;
#pragma unroll
        for (int mt = 0; mt < 2; ++mt) {
            const int rl = wm * 32 + mt * 16 + (l >> 2);
            float rb0 = 0.f, rb1 = 0.f;
            if (MODE == 2) {
                rb0 = rowB[m0 + rl];
                rb1 = rowB[m0 + rl + 8];
            }
#pragma unroll
            for (int nt = 0; nt < 8; ++nt) {
                const int c = wn * 64 + nt * 8 + 2 * (l & 3);
                float v0 = acc[mt][nt][0], v1 = acc[mt][nt][1];
                float v2 = acc[mt][nt][2], v3 = acc[mt][nt][3];
                if (MODE == 1) {
                    const float2 b2 = *(const float2*)&bias[n0 + c];
                    v0 += b2.x; v1 += b2.y; v2 += b2.x; v3 += b2.y;
                } else {
                    v0 = tanh_fast(v0 + rb0); v1 = tanh_fast(v1 + rb0);
                    v2 = tanh_fast(v2 + rb1); v3 = tanh_fast(v3 + rb1);
                }
                pl[(rl * 130 + c) >> 1]       = cvt_h2(v0, v1);
                pl[((rl + 8) * 130 + c) >> 1] = cvt_h2(v2, v3);
            }
        }
        __syncthreads();
        const uint16_t* sm = (const uint16_t*)smem_;
        if (MODE == 1) {
            const long b = m0 / rpb, nIn = m0 - b * rpb;
            plane_out(sm, C16,  m0, 0, ldC, 0);
            plane_out(sm, CT16, b * HA, nIn, ldCT, 1);
        } else {
            plane_out(sm, C16,  m0, n0, ldC, 0);
            plane_out(sm, CT16, n0, m0, ldCT, 1);
        }
    } else {  // MODE 3
        float2 whr[8];
#pragma unroll
        for (int nt = 0; nt < 8; ++nt)
            whr[nt] = *(const float2*)&Wh[wn * 64 + nt * 8 + 2 * (l & 3)];
#pragma unroll
        for (int mt = 0; mt < 2; ++mt) {
            const int rr = wm * 32 + mt * 16 + (l >> 2);
            float s0 = 0.f, s1 = 0.f;
#pragma unroll
            for (int nt = 0; nt < 8; ++nt) {
                const int col = wn * 64 + nt * 8 + 2 * (l & 3);
                const float2 w = whr[nt];
                const float2 p0 = __half22float2(
                    *(const __half2*)&PAdd16[(m0 + rr) * (long)HA + col]);
                const float2 p1 = __half22float2(
                    *(const __half2*)&PAdd16[(m0 + rr + 8) * (long)HA + col]);
                s0 += w.x * tanh_fast(p0.x + acc[mt][nt][0])
                    + w.y * tanh_fast(p0.y + acc[mt][nt][1]);
                s1 += w.x * tanh_fast(p1.x + acc[mt][nt][2])
                    + w.y * tanh_fast(p1.y + acc[mt][nt][3]);
            }
            s0 += __shfl_xor_sync(0xffffffffu, s0, 1);
            s0 += __shfl_xor_sync(0xffffffffu, s0, 2);
            s1 += __shfl_xor_sync(0xffffffffu, s1, 1);
            s1 += __shfl_xor_sync(0xffffffffu, s1, 2);
            if ((l & 3) == 0) {
                sPart[wn][rr]     = s0;
                sPart[wn][rr + 8] = s1;
            }
        }
        __syncthreads();
        if (tid < 128)
            logits[m0 + tid] = sPart[0][tid] + sPart[1][tid] + bh[0];
    }
}

// ============================================================================
// Parallel softmax + weighted sum (X in fp16)
// ============================================================================
__global__ __launch_bounds__(256)
void norm_kernel(const float* __restrict__ logits, float2* __restrict__ norm,
                 int N)
{
    const int b = blockIdx.x;
    logits += (long)b * N;
    __shared__ float sw[2048];
    __shared__ float red[256];
    const int tid = threadIdx.x;

    float mloc = -1e30f;
    for (int i = tid; i < N; i += 256) {
        float v = logits[i];
        sw[i] = v;
        mloc = fmaxf(mloc, v);
    }
    red[tid] = mloc;
    __syncthreads();
    for (int s = 128; s > 0; s >>= 1) {
        if (tid < s) red[tid] = fmaxf(red[tid], red[tid + s]);
        __syncthreads();
    }
    const float m = red[0];
    __syncthreads();

    float sloc = 0.f;
    for (int i = tid; i < N; i += 256)
        sloc += expf(sw[i] - m);
    red[tid] = sloc;
    __syncthreads();
    for (int s = 128; s > 0; s >>= 1) {
        if (tid < s) red[tid] += red[tid + s];
        __syncthreads();
    }
    if (tid == 0) norm[b] = make_float2(m, 1.f / red[0]);
}

__global__ __launch_bounds__(256)
void wsum_kernel(const float* __restrict__ logits, const __half* __restrict__ X,
                 const float2* __restrict__ norm, float* __restrict__ part,
                 int N)
{
    const int b = blockIdx.y, c = blockIdx.x;
    const int CH = N >> 3;
    logits += (long)b * N + c * CH;
    X      += ((long)b * N + (long)c * CH) * HH;

    __shared__ float sw[256];
    const int tid = threadIdx.x;
    const float m = norm[b].x;
    for (int i = tid; i < CH; i += 256)
        sw[i] = expf(logits[i] - m);
    __syncthreads();

    float acc = 0.f;
#pragma unroll 4
    for (int n = 0; n < CH; ++n)
        acc = fmaf(sw[n], __half2float(X[(long)n * HH + tid]), acc);
    part[((b << 3) + c) * HH + tid] = acc;
}

__global__ __launch_bounds__(256)
void reduce_kernel(const float* __restrict__ part,
                   const float2* __restrict__ norm, float* __restrict__ out)
{
    const int b = blockIdx.x, tid = threadIdx.x;
    float s = 0.f;
#pragma unroll
    for (int c = 0; c < 8; ++c)
        s += part[((b << 3) + c) * HH + tid];
    out[(long)b * HH + tid] = s * norm[b].y;
}

// ============================================================================
extern "C" void kernel_launch(void* const* d_in, const int* in_sizes, int n_in,
                              void* d_out, int out_size)
{
    const float* v    = (const float*)d_in[0];
    const float* q    = (const float*)d_in[1];
    const float* Waff = (const float*)d_in[2];
    const float* baff = (const float*)d_in[3];
    const float* Wv   = (const float*)d_in[4];
    const float* bv   = (const float*)d_in[5];
    const float* Wq   = (const float*)d_in[6];
    const float* bq   = (const float*)d_in[7];
    const float* Whv  = (const float*)d_in[8];
    const float* bhv  = (const float*)d_in[9];
    const float* Whq  = (const float*)d_in[10];
    const float* bhq  = (const float*)d_in[11];
    float* out = (float*)d_out;

    __half *v16, *q16, *WaT16, *Wv16, *Wq16, *qW16, *pv16, *pvT16, *pq16,
           *pqT16, *aff16, *afT16;
    float *qb, *lv, *lq, *partv, *partq;
    float2 *nrmv, *nrmq;
    cudaGetSymbolAddress((void**)&v16,   g_v16);
    cudaGetSymbolAddress((void**)&q16,   g_q16);
    cudaGetSymbolAddress((void**)&WaT16, g_WaT16);
    cudaGetSymbolAddress((void**)&Wv16,  g_Wv16);
    cudaGetSymbolAddress((void**)&Wq16,  g_Wq16);
    cudaGetSymbolAddress((void**)&qW16,  g_qW16);
    cudaGetSymbolAddress((void**)&qb,    g_qb);
    cudaGetSymbolAddress((void**)&pv16,  g_pv16);
    cudaGetSymbolAddress((void**)&pvT16, g_pvT16);
    cudaGetSymbolAddress((void**)&pq16,  g_pq16);
    cudaGetSymbolAddress((void**)&pqT16, g_pqT16);
    cudaGetSymbolAddress((void**)&aff16, g_aff16);
    cudaGetSymbolAddress((void**)&afT16, g_afT16);
    cudaGetSymbolAddress((void**)&lv,    g_lv);
    cudaGetSymbolAddress((void**)&lq,    g_lq);
    cudaGetSymbolAddress((void**)&nrmv,  g_normv);
    cudaGetSymbolAddress((void**)&nrmq,  g_normq);
    cudaGetSymbolAddress((void**)&partv, g_partv);
    cudaGetSymbolAddress((void**)&partq, g_partq);

    cudaFuncSetAttribute(mma2<0>, cudaFuncAttributeMaxDynamicSharedMemorySize, DYNSMEM);
    cudaFuncSetAttribute(mma2<1>, cudaFuncAttributeMaxDynamicSharedMemorySize, DYNSMEM);
    cudaFuncSetAttribute(mma2<2>, cudaFuncAttributeMaxDynamicSharedMemorySize, DYNSMEM);
    cudaFuncSetAttribute(mma2<3>, cudaFuncAttributeMaxDynamicSharedMemorySize, DYNSMEM);

    // ---- 4 streams total (proven safe), 2 per pipeline half ----
    cudaStream_t sA[2], sB[2];
    cudaEvent_t eW, eV[2], ePV[2], eAFF[2], eOv[2], eOq[2];
    for (int h = 0; h < 2; ++h) {
        cudaStreamCreateWithFlags(&sA[h], cudaStreamNonBlocking);
        cudaStreamCreateWithFlags(&sB[h], cudaStreamNonBlocking);
        cudaEventCreateWithFlags(&eV[h],   cudaEventDisableTiming);
        cudaEventCreateWithFlags(&ePV[h],  cudaEventDisableTiming);
        cudaEventCreateWithFlags(&eAFF[h], cudaEventDisableTiming);
        cudaEventCreateWithFlags(&eOv[h],  cudaEventDisableTiming);
        cudaEventCreateWithFlags(&eOq[h],  cudaEventDisableTiming);
    }
    cudaEventCreateWithFlags(&eW, cudaEventDisableTiming);

    // weight preps on the capturing (default) stream
    cvtT_kernel<<<(HH*HH)/256, 256>>>(Waff, WaT16, HH, HH);
    cvt_kernel<<<(HA*HH)/1024, 256>>>(Wv, Wv16, HA*HH);
    cvt_kernel<<<(HA*HH)/1024, 256>>>(Wq, Wq16, HA*HH);
    cudaEventRecord(eW, 0);

    for (int h = 0; h < 2; ++h) {
        const long z0 = (long)h * BH;
        const long oVH = z0 * NV * HH, oQH = z0 * NQ * HH;
        const long oPV = z0 * NV * HA, oPVT = z0 * HA * NV;
        const long oPQ = z0 * NQ * HA, oPQT = z0 * HA * NQ;
        const long oAF = z0 * NQ * NV, oAFT = z0 * NV * NQ;
        const long oLV = z0 * NV, oLQ = z0 * NQ;

        // sA: cvt_v -> pv(+pvT) -> [aff] -> G5 chain
        cudaStreamWaitEvent(sA[h], eW, 0);
        cvt_kernel<<<(BH*NV*HH)/1024, 256, 0, sA[h]>>>(
            v + oVH, v16 + oVH, (long)BH*NV*HH);
        cudaEventRecord(eV[h], sA[h]);
        mma2<1><<<dim3(1, BH*NV/128, 1), 256, DYNSMEM, sA[h]>>>(
            v16 + oVH, Wv16, bv, nullptr, pv16 + oPV, pvT16 + oPVT, nullptr,
            nullptr, nullptr, nullptr,
            HH, HH, HH, HA, NV, NV, 0, 0, 0, 0, 0, 0);
        cudaEventRecord(ePV[h], sA[h]);

        // sB: cvt_q -> qb -> qW -> pq(+pqT) -> [v16] aff -> [pv] G6 chain
        cudaStreamWaitEvent(sB[h], eW, 0);
        cvt_kernel<<<(BH*NQ*HH)/1024, 256, 0, sB[h]>>>(
            q + oQH, q16 + oQH, (long)BH*NQ*HH);
        qb_kernel<<<(BH*NQ)/8, 256, 0, sB[h]>>>(
            q + oQH, baff, qb + oLQ, BH*NQ);
        mma2<0><<<dim3(HH/128, BH*NQ/128, 1), 256, DYNSMEM, sB[h]>>>(
            q16 + oQH, WaT16, nullptr, nullptr, qW16 + oQH, nullptr, nullptr,
            nullptr, nullptr, nullptr,
            HH, HH, HH, HH, 0, 0, 0, 0, 0, 0, 0, 0);
        mma2<1><<<dim3(1, BH*NQ/128, 1), 256, DYNSMEM, sB[h]>>>(
            q16 + oQH, Wq16, bq, nullptr, pq16 + oPQ, pqT16 + oPQT, nullptr,
            nullptr, nullptr, nullptr,
            HH, HH, HH, HA, NQ, NQ, 0, 0, 0, 0, 0, 0);
        cudaStreamWaitEvent(sB[h], eV[h], 0);
        mma2<2><<<dim3(NV/128, NQ/128, BH), 256, DYNSMEM, sB[h]>>>(
            qW16 + oQH, v16 + oVH, nullptr, qb + oLQ,
            aff16 + oAF, afT16 + oAFT, nullptr, nullptr, nullptr, nullptr,
            HH, HH, HH, NV, NQ, 0,
            (long)NQ*HH, (long)NV*HH, (long)NQ*NV, (long)NV*NQ, 0, 0);
        cudaEventRecord(eAFF[h], sB[h]);

        // sA: G5 chain (aff event implies pq/pqT done; pv in-stream)
        cudaStreamWaitEvent(sA[h], eAFF[h], 0);
        mma2<3><<<dim3(NV/128, 1, BH), 256, DYNSMEM, sA[h]>>>(
            afT16 + oAFT, pqT16 + oPQT, nullptr, nullptr, nullptr, nullptr,
            pv16 + oPV, Whv, bhv, lv + oLV,
            NQ, NQ, NQ, 0, 0, 0,
            (long)NV*NQ, (long)HA*NQ, 0, 0, (long)NV*HA, NV);
        norm_kernel<<<BH, 256, 0, sA[h]>>>(lv + oLV, nrmv + z0, NV);
        wsum_kernel<<<dim3(8, BH), 256, 0, sA[h]>>>(
            lv + oLV, v16 + oVH, nrmv + z0, partv + z0*8*HH, NV);
        reduce_kernel<<<BH, 256, 0, sA[h]>>>(
            partv + z0*8*HH, nrmv + z0, out + z0*HH);
        cudaEventRecord(eOv[h], sA[h]);

        // sB: G6 chain (aff in-stream; needs pvT cross-stream)
        cudaStreamWaitEvent(sB[h], ePV[h], 0);
        mma2<3><<<dim3(NQ/128, 1, BH), 256, DYNSMEM, sB[h]>>>(
            aff16 + oAF, pvT16 + oPVT, nullptr, nullptr, nullptr, nullptr,
            pq16 + oPQ, Whq, bhq, lq + oLQ,
            NV, NV, NV, 0, 0, 0,
            (long)NQ*NV, (long)HA*NV, 0, 0, (long)NQ*HA, NQ);
        norm_kernel<<<BH, 256, 0, sB[h]>>>(lq + oLQ, nrmq + z0, NQ);
        wsum_kernel<<<dim3(8, BH), 256, 0, sB[h]>>>(
            lq + oLQ, q16 + oQH, nrmq + z0, partq + z0*8*HH, NQ);
        reduce_kernel<<<BH, 256, 0, sB[h]>>>(
            partq + z0*8*HH, nrmq + z0, out + (long)BB*HH + z0*HH);
        cudaEventRecord(eOq[h], sB[h]);
    }

    for (int h = 0; h < 2; ++h) {
        cudaStreamWaitEvent(0, eOv[h], 0);
        cudaStreamWaitEvent(0, eOq[h], 0);
    }

    for (int h = 0; h < 2; ++h) {
        cudaStreamDestroy(sA[h]); cudaStreamDestroy(sB[h]);
        cudaEventDestroy(eV[h]);  cudaEventDestroy(ePV[h]);
        cudaEventDestroy(eAFF[h]);
        cudaEventDestroy(eOv[h]); cudaEventDestroy(eOq[h]);
    }
    cudaEventDestroy(eW);
}

// round 17
// speedup vs baseline: 1.3201x; 1.1132x over previous
#include <cuda_runtime.h>
#include <cuda_fp16.h>
#include <cstdint>
#include <math.h>

#define BB  64
#define NV  2048
#define NQ  512
#define HH  256
#define HA  128
#define BH  32          // batches per pipeline half

// ---------------- scratch (device globals) ---------------------------------
__device__ __half g_v16[(size_t)BB*NV*HH];
__device__ __half g_q16[(size_t)BB*NQ*HH];
__device__ __half g_WaT16[HH*HH];
__device__ __half g_Wv16[HA*HH], g_Wq16[HA*HH];
__device__ __half g_qW16[(size_t)BB*NQ*HH];
__device__ float  g_qb[BB*NQ];
__device__ __half g_pv16[(size_t)BB*NV*HA];
__device__ __half g_pvT16[(size_t)BB*HA*NV];
__device__ __half g_pq16[(size_t)BB*NQ*HA];
__device__ __half g_pqT16[(size_t)BB*HA*NQ];
__device__ __half g_aff16[(size_t)BB*NQ*NV];
__device__ __half g_afT16[(size_t)BB*NV*NQ];
__device__ float  g_lv[BB*NV], g_lq[BB*NQ];
__device__ float2 g_normv[BB], g_normq[BB];
__device__ float  g_partv[BB*8*HH], g_partq[BB*8*HH];

// BK=64: rows of 64 fp16 = 128B data + 16B pad = 144B stride
#define RSTR     144
#define TILE_B   (128 * RSTR)          // 18432
#define BUF_B    (2 * TILE_B)          // 36864 (A + B tiles)
#define DYNSMEM  (2 * BUF_B)           // 73728 (double buffered)
#define PLANE_B  33280

// ======================= low-level helpers =================================
__device__ __forceinline__ uint32_t smem_u32(const void* p) {
    uint32_t a;
    asm("{ .reg .u64 t; cvta.to.shared.u64 t, %1; cvt.u32.u64 %0, t; }"
        : "=r"(a) : "l"(p));
    return a;
}
__device__ __forceinline__ void ldsm4(uint32_t* r, uint32_t a) {
    asm volatile("ldmatrix.sync.aligned.m8n8.x4.shared.b16 {%0,%1,%2,%3}, [%4];"
                 : "=r"(r[0]), "=r"(r[1]), "=r"(r[2]), "=r"(r[3]) : "r"(a));
}
__device__ __forceinline__ void mma_f16(float* c, const uint32_t* a,
                                        const uint32_t* b) {
    asm volatile(
        "mma.sync.aligned.m16n8k16.row.col.f32.f16.f16.f32 "
        "{%0,%1,%2,%3}, {%4,%5,%6,%7}, {%8,%9}, {%0,%1,%2,%3};"
        : "+f"(c[0]), "+f"(c[1]), "+f"(c[2]), "+f"(c[3])
        : "r"(a[0]), "r"(a[1]), "r"(a[2]), "r"(a[3]), "r"(b[0]), "r"(b[1]));
}
__device__ __forceinline__ uint32_t cvt_h2(float x, float y) {
    uint32_t r;
    asm("cvt.rn.f16x2.f32 %0, %1, %2;" : "=r"(r) : "f"(y), "f"(x));
    return r;
}
__device__ __forceinline__ float tanh_fast(float x) {
    float e = __expf(2.0f * x);
    return 1.0f - __fdividef(2.0f, e + 1.0f);
}

// cp.async stage: 2 tiles (A, B), each 128 rows x 128B data -> 144B rows
__device__ __forceinline__ void stage_async(uint32_t buf,
        const __half* __restrict__ A, const __half* __restrict__ B,
        int lda, int ldb, int k0) {
    const int tid = threadIdx.x;
#pragma unroll
    for (int c = 0; c < 8; ++c) {
        const int lin = c * 256 + tid;       // 0..2047
        const int sel = lin >> 10;           // 0:A 1:B (1024 xfers per tile)
        const int li  = lin & 1023;
        const int row = li >> 3, qt = li & 7;
        const __half* src = sel ? B : A;
        const int ld = sel ? ldb : lda;
        asm volatile("cp.async.cg.shared.global [%0], [%1], 16;"
            :: "r"(buf + sel * TILE_B + row * RSTR + qt * 16),
               "l"((const char*)(src + (long)row * ld + k0) + qt * 16));
    }
}

__device__ __forceinline__ void plane_out(const uint16_t* __restrict__ sm,
                                          __half* __restrict__ dst,
                                          long row0, long col0, long ld, int tr) {
    const int tid = threadIdx.x;
#pragma unroll
    for (int cI = 0; cI < 8; ++cI) {
        const int g = cI * 256 + tid;
        const int r = g >> 4, ch = g & 15;
        uint16_t e[8];
#pragma unroll
        for (int i = 0; i < 8; ++i)
            e[i] = tr ? sm[(ch * 8 + i) * 130 + r] : sm[r * 130 + ch * 8 + i];
        uint4 w;
        w.x = e[0] | ((uint32_t)e[1] << 16);
        w.y = e[2] | ((uint32_t)e[3] << 16);
        w.z = e[4] | ((uint32_t)e[5] << 16);
        w.w = e[6] | ((uint32_t)e[7] << 16);
        *(uint4*)(dst + (row0 + r) * ld + col0 + ch * 8) = w;
    }
}

// ============================================================================
// prep kernels
// ============================================================================
__global__ __launch_bounds__(256)
void cvt_kernel(const float* __restrict__ x, __half* __restrict__ o, long n)
{
    const long i = ((long)blockIdx.x * 256 + threadIdx.x) * 4;
    if (i >= n) return;
    const float4 v = *(const float4*)(x + i);
    *(uint2*)((uint32_t*)o + (i >> 1)) =
        make_uint2(cvt_h2(v.x, v.y), cvt_h2(v.z, v.w));
}

__global__ __launch_bounds__(256)
void cvtT_kernel(const float* __restrict__ x, __half* __restrict__ o,
                 int R, int C)
{
    const int i = blockIdx.x * 256 + threadIdx.x;
    if (i >= R * C) return;
    const int r = i / C, c = i - r * C;
    o[(long)c * R + r] = __float2half(x[i]);
}

__global__ __launch_bounds__(256)
void qb_kernel(const float* __restrict__ q, const float* __restrict__ baff,
               float* __restrict__ qb, int rows)
{
    const int w = (blockIdx.x * 256 + threadIdx.x) >> 5;
    const int lane = threadIdx.x & 31;
    if (w >= rows) return;
    const float* r = q + (long)w * HH;
    float s = 0.f;
#pragma unroll
    for (int k = 0; k < 8; ++k)
        s += r[lane + 32 * k] * baff[lane + 32 * k];
#pragma unroll
    for (int off = 16; off > 0; off >>= 1)
        s += __shfl_xor_sync(0xffffffffu, s, off);
    if (lane == 0) qb[w] = s;
}

// ============================================================================
// mma2: C = A @ B^T (fp16 in, fp32 acc), 128x128x64 tile, 8 warps, 2 CTA/SM.
// MODE 0: C16 = f16(acc [+bias]) direct                      [qW]
// MODE 1: C16 = f16(acc + bias) + CT16 transposed (planes)   [pv,pq]
// MODE 2: C16 = f16(tanh(acc + rowB)) + CT16 transposed      [aff]
// MODE 3: logits[m] = Wh . tanh(f32(PAdd16[m]) + acc[m]) + bh
// ============================================================================
template<int MODE>
__global__ __launch_bounds__(256, 2)
void mma2(const __half* __restrict__ A, const __half* __restrict__ B,
          const float* __restrict__ bias, const float* __restrict__ rowB,
          __half* __restrict__ C16, __half* __restrict__ CT16,
          const __half* __restrict__ PAdd16,
          const float* __restrict__ Wh, const float* __restrict__ bh,
          float* __restrict__ logits,
          int K, int lda, int ldb, int ldC, int ldCT, int rpb,
          long sA, long sB, long sOC, long sOCT, long sPAdd, int sLog)
{
    extern __shared__ __align__(16) unsigned char smem_[];
    __shared__ float sPart[2][128];

    const int z = blockIdx.z;
    A += z * sA;  B += z * sB;
    if (MODE == 2) { C16 += z * sOC; CT16 += z * sOCT; rowB += (long)z * NQ; }
    if (MODE == 3) { PAdd16 += z * sPAdd; logits += (long)z * sLog; }

    const long m0 = (long)(MODE == 3 ? blockIdx.x : blockIdx.y) * 128;
    const long n0 = (MODE == 3) ? 0 : (long)blockIdx.x * 128;
    A += m0 * lda;  B += n0 * ldb;

    const uint32_t sb0 = smem_u32(smem_);
    const int tid = threadIdx.x;
    const int l = tid & 31, wid = tid >> 5;
    const int wm = wid & 3, wn = wid >> 2;

    const int sub = l >> 3, lr = l & 7;
    const uint32_t aRow = wm * 32 + ((sub & 1) << 3) + lr;
    const uint32_t aK   = (uint32_t)((sub >> 1) << 3);
    const uint32_t bRow = ((sub & 2) << 2) + lr;
    const uint32_t bK   = (uint32_t)((sub & 1) << 3);

    float acc[2][8][4] = {};

    stage_async(sb0, A, B, lda, ldb, 0);
    asm volatile("cp.async.commit_group;" ::: "memory");

    const int nchunk = K >> 6;
    for (int ch = 0; ch < nchunk; ++ch) {
        if (ch + 1 < nchunk) {
            stage_async(sb0 + ((ch + 1) & 1) * BUF_B, A, B, lda, ldb,
                        (ch + 1) * 64);
            asm volatile("cp.async.commit_group;" ::: "memory");
            asm volatile("cp.async.wait_group 1;" ::: "memory");
        } else {
            asm volatile("cp.async.wait_group 0;" ::: "memory");
        }
        __syncthreads();

        const uint32_t cur = sb0 + (ch & 1) * BUF_B;
        const uint32_t sA = cur, sB = cur + TILE_B;

#pragma unroll
        for (int kt = 0; kt < 64; kt += 16) {
            uint32_t Af[2][4];
            const uint32_t ak = (kt + aK) * 2;
#pragma unroll
            for (int mt = 0; mt < 2; ++mt)
                ldsm4(Af[mt], sA + (aRow + mt * 16) * RSTR + ak);
            const uint32_t bk = (kt + bK) * 2;
#pragma unroll
            for (int g = 0; g < 4; ++g) {
                uint32_t Bf[4];
                ldsm4(Bf, sB + (wn * 64 + g * 16 + bRow) * RSTR + bk);
                mma_f16(acc[0][2*g],   Af[0], &Bf[0]);
                mma_f16(acc[0][2*g+1], Af[0], &Bf[2]);
                mma_f16(acc[1][2*g],   Af[1], &Bf[0]);
                mma_f16(acc[1][2*g+1], Af[1], &Bf[2]);
            }
        }
        __syncthreads();
    }

    // ---------------- epilogues ----------------
    if (MODE == 0) {
#pragma unroll
        for (int mt = 0; mt < 2; ++mt) {
            const long r0 = m0 + wm * 32 + mt * 16 + (l >> 2);
#pragma unroll
            for (int nt = 0; nt < 8; ++nt) {
                const long col = n0 + wn * 64 + nt * 8 + 2 * (l & 3);
                float2 b2 = bias ? *(const float2*)&bias[col]
                                 : make_float2(0.f, 0.f);
                ((uint32_t*)C16)[(r0 * (long)ldC + col) >> 1] =
                    cvt_h2(acc[mt][nt][0] + b2.x, acc[mt][nt][1] + b2.y);
                ((uint32_t*)C16)[((r0 + 8) * (long)ldC + col) >> 1] =
                    cvt_h2(acc[mt][nt][2] + b2.x, acc[mt][nt][3] + b2.y);
            }
        }
    } else if (MODE == 1 || MODE == 2) {
        uint32_t* pl = (uint32_t*)smem_;
#pragma unroll
        for (int mt = 0; mt < 2; ++mt) {
            const int rl = wm * 32 + mt * 16 + (l >> 2);
            float rb0 = 0.f, rb1 = 0.f;
            if (MODE == 2) {
                rb0 = rowB[m0 + rl];
                rb1 = rowB[m0 + rl + 8];
            }
#pragma unroll
            for (int nt = 0; nt < 8; ++nt) {
                const int c = wn * 64 + nt * 8 + 2 * (l & 3);
                float v0 = acc[mt][nt][0], v1 = acc[mt][nt][1];
                float v2 = acc[mt][nt][2], v3 = acc[mt][nt][3];
                if (MODE == 1) {
                    const float2 b2 = *(const float2*)&bias[n0 + c];
                    v0 += b2.x; v1 += b2.y; v2 += b2.x; v3 += b2.y;
                } else {
                    v0 = tanh_fast(v0 + rb0); v1 = tanh_fast(v1 + rb0);
                    v2 = tanh_fast(v2 + rb1); v3 = tanh_fast(v3 + rb1);
                }
                pl[(rl * 130 + c) >> 1]       = cvt_h2(v0, v1);
                pl[((rl + 8) * 130 + c) >> 1] = cvt_h2(v2, v3);
            }
        }
        __syncthreads();
        const uint16_t* sm = (const uint16_t*)smem_;
        if (MODE == 1) {
            const long b = m0 / rpb, nIn = m0 - b * rpb;
            plane_out(sm, C16,  m0, 0, ldC, 0);
            plane_out(sm, CT16, b * HA, nIn, ldCT, 1);
        } else {
            plane_out(sm, C16,  m0, n0, ldC, 0);
            plane_out(sm, CT16, n0, m0, ldCT, 1);
        }
    } else {  // MODE 3
        float2 whr[8];
#pragma unroll
        for (int nt = 0; nt < 8; ++nt)
            whr[nt] = *(const float2*)&Wh[wn * 64 + nt * 8 + 2 * (l & 3)];
#pragma unroll
        for (int mt = 0; mt < 2; ++mt) {
            const int rr = wm * 32 + mt * 16 + (l >> 2);
            float s0 = 0.f, s1 = 0.f;
#pragma unroll
            for (int nt = 0; nt < 8; ++nt) {
                const int col = wn * 64 + nt * 8 + 2 * (l & 3);
                const float2 w = whr[nt];
                const float2 p0 = __half22float2(
                    *(const __half2*)&PAdd16[(m0 + rr) * (long)HA + col]);
                const float2 p1 = __half22float2(
                    *(const __half2*)&PAdd16[(m0 + rr + 8) * (long)HA + col]);
                s0 += w.x * tanh_fast(p0.x + acc[mt][nt][0])
                    + w.y * tanh_fast(p0.y + acc[mt][nt][1]);
                s1 += w.x * tanh_fast(p1.x + acc[mt][nt][2])
                    + w.y * tanh_fast(p1.y + acc[mt][nt][3]);
            }
            s0 += __shfl_xor_sync(0xffffffffu, s0, 1);
            s0 += __shfl_xor_sync(0xffffffffu, s0, 2);
            s1 += __shfl_xor_sync(0xffffffffu, s1, 1);
            s1 += __shfl_xor_sync(0xffffffffu, s1, 2);
            if ((l & 3) == 0) {
                sPart[wn][rr]     = s0;
                sPart[wn][rr + 8] = s1;
            }
        }
        __syncthreads();
        if (tid < 128)
            logits[m0 + tid] = sPart[0][tid] + sPart[1][tid] + bh[0];
    }
}

// ============================================================================
// Parallel softmax + weighted sum (X in fp16)
// ============================================================================
__global__ __launch_bounds__(256)
void norm_kernel(const float* __restrict__ logits, float2* __restrict__ norm,
                 int N)
{
    const int b = blockIdx.x;
    logits += (long)b * N;
    __shared__ float sw[2048];
    __shared__ float red[256];
    const int tid = threadIdx.x;

    float mloc = -1e30f;
    for (int i = tid; i < N; i += 256) {
        float v = logits[i];
        sw[i] = v;
        mloc = fmaxf(mloc, v);
    }
    red[tid] = mloc;
    __syncthreads();
    for (int s = 128; s > 0; s >>= 1) {
        if (tid < s) red[tid] = fmaxf(red[tid], red[tid + s]);
        __syncthreads();
    }
    const float m = red[0];
    __syncthreads();

    float sloc = 0.f;
    for (int i = tid; i < N; i += 256)
        sloc += expf(sw[i] - m);
    red[tid] = sloc;
    __syncthreads();
    for (int s = 128; s > 0; s >>= 1) {
        if (tid < s) red[tid] += red[tid + s];
        __syncthreads();
    }
    if (tid == 0) norm[b] = make_float2(m, 1.f / red[0]);
}

__global__ __launch_bounds__(256)
void wsum_kernel(const float* __restrict__ logits, const __half* __restrict__ X,
                 const float2* __restrict__ norm, float* __restrict__ part,
                 int N)
{
    const int b = blockIdx.y, c = blockIdx.x;
    const int CH = N >> 3;
    logits += (long)b * N + c * CH;
    X      += ((long)b * N + (long)c * CH) * HH;

    __shared__ float sw[256];
    const int tid = threadIdx.x;
    const float m = norm[b].x;
    for (int i = tid; i < CH; i += 256)
        sw[i] = expf(logits[i] - m);
    __syncthreads();

    float acc = 0.f;
#pragma unroll 4
    for (int n = 0; n < CH; ++n)
        acc = fmaf(sw[n], __half2float(X[(long)n * HH + tid]), acc);
    part[((b << 3) + c) * HH + tid] = acc;
}

__global__ __launch_bounds__(256)
void reduce_kernel(const float* __restrict__ part,
                   const float2* __restrict__ norm, float* __restrict__ out)
{
    const int b = blockIdx.x, tid = threadIdx.x;
    float s = 0.f;
#pragma unroll
    for (int c = 0; c < 8; ++c)
        s += part[((b << 3) + c) * HH + tid];
    out[(long)b * HH + tid] = s * norm[b].y;
}

// ============================================================================
extern "C" void kernel_launch(void* const* d_in, const int* in_sizes, int n_in,
                              void* d_out, int out_size)
{
    const float* v    = (const float*)d_in[0];
    const float* q    = (const float*)d_in[1];
    const float* Waff = (const float*)d_in[2];
    const float* baff = (const float*)d_in[3];
    const float* Wv   = (const float*)d_in[4];
    const float* bv   = (const float*)d_in[5];
    const float* Wq   = (const float*)d_in[6];
    const float* bq   = (const float*)d_in[7];
    const float* Whv  = (const float*)d_in[8];
    const float* bhv  = (const float*)d_in[9];
    const float* Whq  = (const float*)d_in[10];
    const float* bhq  = (const float*)d_in[11];
    float* out = (float*)d_out;

    __half *v16, *q16, *WaT16, *Wv16, *Wq16, *qW16, *pv16, *pvT16, *pq16,
           *pqT16, *aff16, *afT16;
    float *qb, *lv, *lq, *partv, *partq;
    float2 *nrmv, *nrmq;
    cudaGetSymbolAddress((void**)&v16,   g_v16);
    cudaGetSymbolAddress((void**)&q16,   g_q16);
    cudaGetSymbolAddress((void**)&WaT16, g_WaT16);
    cudaGetSymbolAddress((void**)&Wv16,  g_Wv16);
    cudaGetSymbolAddress((void**)&Wq16,  g_Wq16);
    cudaGetSymbolAddress((void**)&qW16,  g_qW16);
    cudaGetSymbolAddress((void**)&qb,    g_qb);
    cudaGetSymbolAddress((void**)&pv16,  g_pv16);
    cudaGetSymbolAddress((void**)&pvT16, g_pvT16);
    cudaGetSymbolAddress((void**)&pq16,  g_pq16);
    cudaGetSymbolAddress((void**)&pqT16, g_pqT16);
    cudaGetSymbolAddress((void**)&aff16, g_aff16);
    cudaGetSymbolAddress((void**)&afT16, g_afT16);
    cudaGetSymbolAddress((void**)&lv,    g_lv);
    cudaGetSymbolAddress((void**)&lq,    g_lq);
    cudaGetSymbolAddress((void**)&nrmv,  g_normv);
    cudaGetSymbolAddress((void**)&nrmq,  g_normq);
    cudaGetSymbolAddress((void**)&partv, g_partv);
    cudaGetSymbolAddress((void**)&partq, g_partq);

    cudaFuncSetAttribute(mma2<0>, cudaFuncAttributeMaxDynamicSharedMemorySize, DYNSMEM);
    cudaFuncSetAttribute(mma2<1>, cudaFuncAttributeMaxDynamicSharedMemorySize, DYNSMEM);
    cudaFuncSetAttribute(mma2<2>, cudaFuncAttributeMaxDynamicSharedMemorySize, DYNSMEM);
    cudaFuncSetAttribute(mma2<3>, cudaFuncAttributeMaxDynamicSharedMemorySize, DYNSMEM);

    // ---- 4 streams total (proven safe), 2 per pipeline half ----
    cudaStream_t sA[2], sB[2];
    cudaEvent_t eW, eV[2], ePV[2], eAFF[2], eOv[2], eOq[2];
    for (int h = 0; h < 2; ++h) {
        cudaStreamCreateWithFlags(&sA[h], cudaStreamNonBlocking);
        cudaStreamCreateWithFlags(&sB[h], cudaStreamNonBlocking);
        cudaEventCreateWithFlags(&eV[h],   cudaEventDisableTiming);
        cudaEventCreateWithFlags(&ePV[h],  cudaEventDisableTiming);
        cudaEventCreateWithFlags(&eAFF[h], cudaEventDisableTiming);
        cudaEventCreateWithFlags(&eOv[h],  cudaEventDisableTiming);
        cudaEventCreateWithFlags(&eOq[h],  cudaEventDisableTiming);
    }
    cudaEventCreateWithFlags(&eW, cudaEventDisableTiming);

    // weight preps on the capturing (default) stream
    cvtT_kernel<<<(HH*HH)/256, 256>>>(Waff, WaT16, HH, HH);
    cvt_kernel<<<(HA*HH)/1024, 256>>>(Wv, Wv16, HA*HH);
    cvt_kernel<<<(HA*HH)/1024, 256>>>(Wq, Wq16, HA*HH);
    cudaEventRecord(eW, 0);

    for (int h = 0; h < 2; ++h) {
        const long z0 = (long)h * BH;
        const long oVH = z0 * NV * HH, oQH = z0 * NQ * HH;
        const long oPV = z0 * NV * HA, oPVT = z0 * HA * NV;
        const long oPQ = z0 * NQ * HA, oPQT = z0 * HA * NQ;
        const long oAF = z0 * NQ * NV, oAFT = z0 * NV * NQ;
        const long oLV = z0 * NV, oLQ = z0 * NQ;

        // sA: cvt_v -> pv(+pvT) -> [aff] -> G5 chain
        cudaStreamWaitEvent(sA[h], eW, 0);
        cvt_kernel<<<(BH*NV*HH)/1024, 256, 0, sA[h]>>>(
            v + oVH, v16 + oVH, (long)BH*NV*HH);
        cudaEventRecord(eV[h], sA[h]);
        mma2<1><<<dim3(1, BH*NV/128, 1), 256, DYNSMEM, sA[h]>>>(
            v16 + oVH, Wv16, bv, nullptr, pv16 + oPV, pvT16 + oPVT, nullptr,
            nullptr, nullptr, nullptr,
            HH, HH, HH, HA, NV, NV, 0, 0, 0, 0, 0, 0);
        cudaEventRecord(ePV[h], sA[h]);

        // sB: cvt_q -> qb -> qW -> pq(+pqT) -> [v16] aff -> [pv] G6 chain
        cudaStreamWaitEvent(sB[h], eW, 0);
        cvt_kernel<<<(BH*NQ*HH)/1024, 256, 0, sB[h]>>>(
            q + oQH, q16 + oQH, (long)BH*NQ*HH);
        qb_kernel<<<(BH*NQ)/8, 256, 0, sB[h]>>>(
            q + oQH, baff, qb + oLQ, BH*NQ);
        mma2<0><<<dim3(HH/128, BH*NQ/128, 1), 256, DYNSMEM, sB[h]>>>(
            q16 + oQH, WaT16, nullptr, nullptr, qW16 + oQH, nullptr, nullptr,
            nullptr, nullptr, nullptr,
            HH, HH, HH, HH, 0, 0, 0, 0, 0, 0, 0, 0);
        mma2<1><<<dim3(1, BH*NQ/128, 1), 256, DYNSMEM, sB[h]>>>(
            q16 + oQH, Wq16, bq, nullptr, pq16 + oPQ, pqT16 + oPQT, nullptr,
            nullptr, nullptr, nullptr,
            HH, HH, HH, HA, NQ, NQ, 0, 0, 0, 0, 0, 0);
        cudaStreamWaitEvent(sB[h], eV[h], 0);
        mma2<2><<<dim3(NV/128, NQ/128, BH), 256, DYNSMEM, sB[h]>>>(
            qW16 + oQH, v16 + oVH, nullptr, qb + oLQ,
            aff16 + oAF, afT16 + oAFT, nullptr, nullptr, nullptr, nullptr,
            HH, HH, HH, NV, NQ, 0,
            (long)NQ*HH, (long)NV*HH, (long)NQ*NV, (long)NV*NQ, 0, 0);
        cudaEventRecord(eAFF[h], sB[h]);

        // sA: G5 chain (aff event implies pq/pqT done; pv in-stream)
        cudaStreamWaitEvent(sA[h], eAFF[h], 0);
        mma2<3><<<dim3(NV/128, 1, BH), 256, DYNSMEM, sA[h]>>>(
            afT16 + oAFT, pqT16 + oPQT, nullptr, nullptr, nullptr, nullptr,
            pv16 + oPV, Whv, bhv, lv + oLV,
            NQ, NQ, NQ, 0, 0, 0,
            (long)NV*NQ, (long)HA*NQ, 0, 0, (long)NV*HA, NV);
        norm_kernel<<<BH, 256, 0, sA[h]>>>(lv + oLV, nrmv + z0, NV);
        wsum_kernel<<<dim3(8, BH), 256, 0, sA[h]>>>(
            lv + oLV, v16 + oVH, nrmv + z0, partv + z0*8*HH, NV);
        reduce_kernel<<<BH, 256, 0, sA[h]>>>(
            partv + z0*8*HH, nrmv + z0, out + z0*HH);
        cudaEventRecord(eOv[h], sA[h]);

        // sB: G6 chain (aff in-stream; needs pvT cross-stream)
        cudaStreamWaitEvent(sB[h], ePV[h], 0);
        mma2<3><<<dim3(NQ/128, 1, BH), 256, DYNSMEM, sB[h]>>>(
            aff16 + oAF, pvT16 + oPVT, nullptr, nullptr, nullptr, nullptr,
            pq16 + oPQ, Whq, bhq, lq + oLQ,
            NV, NV, NV, 0, 0, 0,
            (long)NQ*NV, (long)HA*NV, 0, 0, (long)NQ*HA, NQ);
        norm_kernel<<<BH, 256, 0, sB[h]>>>(lq + oLQ, nrmq + z0, NQ);
        wsum_kernel<<<dim3(8, BH), 256, 0, sB[h]>>>(
            lq + oLQ, q16 + oQH, nrmq + z0, partq + z0*8*HH, NQ);
        reduce_kernel<<<BH, 256, 0, sB[h]>>>(
            partq + z0*8*HH, nrmq + z0, out + (long)BB*HH + z0*HH);
        cudaEventRecord(eOq[h], sB[h]);
    }

    for (int h = 0; h < 2; ++h) {
        cudaStreamWaitEvent(0, eOv[h], 0);
        cudaStreamWaitEvent(0, eOq[h], 0);
    }

    for (int h = 0; h < 2; ++h) {
        cudaStreamDestroy(sA[h]); cudaStreamDestroy(sB[h]);
        cudaEventDestroy(eV[h]);  cudaEventDestroy(ePV[h]);
        cudaEventDestroy(eAFF[h]);
        cudaEventDestroy(eOv[h]); cudaEventDestroy(eOq[h]);
    }
    cudaEventDestroy(eW);
}